// round 1
// baseline (speedup 1.0000x reference)
#include <cuda_runtime.h>
#include <math.h>

#define Bn   4
#define CIN  256
#define CQK  64
#define CS   128
#define Hh   128
#define Ww   128
#define HW   (Hh*Ww)
#define NCH  32                    // split-N chunks for sim reduction
#define PIX_PER_CHUNK (HW/NCH)     // 512

// ---- scratch (static device arrays; no allocation in kernel_launch) ----
__device__ float g_qn  [Bn*CQK*HW];          // 16 MB
__device__ float g_kn  [Bn*CQK*HW];          // 16 MB
__device__ float g_v   [Bn*CIN*HW];          // 64 MB
__device__ float g_fuse[Bn*CIN*HW];          // 64 MB
__device__ float g_simp[Bn*NCH*CQK*CIN];     // 8 MB
__device__ float g_sim [Bn*CQK*CIN];
__device__ float g_M2  [Bn*CIN*CQK];

// ============================================================
// K1: q,k projections (stacked 128x256 GEMM) + BN + per-pixel L2 norm
// grid (HW/128, B), block 256
// ============================================================
__global__ void k_qk(const float* __restrict__ x,
                     const float* __restrict__ qW, const float* __restrict__ qs, const float* __restrict__ qb,
                     const float* __restrict__ kW, const float* __restrict__ ks, const float* __restrict__ kb)
{
    __shared__ float Wt[128][16];
    __shared__ float Xt[16][128];
    __shared__ float Ps[16][128];
    __shared__ float Nn[2][128];

    const int b  = blockIdx.y;
    const int n0 = blockIdx.x * 128;
    const int tid = threadIdx.x;
    const int ty = tid >> 4, tx = tid & 15;

    float acc[8][8];
#pragma unroll
    for (int r = 0; r < 8; r++)
#pragma unroll
        for (int c = 0; c < 8; c++) acc[r][c] = 0.f;

    const float* xb = x + (size_t)b * CIN * HW;

    for (int kk = 0; kk < CIN; kk += 16) {
#pragma unroll
        for (int i = 0; i < 8; i++) {
            int idx = i * 256 + tid;
            int m = idx >> 4, kl = idx & 15;
            Wt[m][kl] = (m < 64) ? qW[m * CIN + kk + kl]
                                 : kW[(m - 64) * CIN + kk + kl];
        }
#pragma unroll
        for (int i = 0; i < 8; i++) {
            int idx = i * 256 + tid;
            int r = idx >> 7, c = idx & 127;
            Xt[r][c] = xb[(size_t)(kk + r) * HW + n0 + c];
        }
        __syncthreads();
#pragma unroll
        for (int k = 0; k < 16; k++) {
            float wr[8], xr[8];
#pragma unroll
            for (int r = 0; r < 8; r++) wr[r] = Wt[ty * 8 + r][k];
#pragma unroll
            for (int c = 0; c < 8; c++) xr[c] = Xt[k][tx * 8 + c];
#pragma unroll
            for (int r = 0; r < 8; r++)
#pragma unroll
                for (int c = 0; c < 8; c++) acc[r][c] = fmaf(wr[r], xr[c], acc[r][c]);
        }
        __syncthreads();
    }

    // BN + partial column sums of squares (deterministic, no atomics)
    float colsq[8];
#pragma unroll
    for (int c = 0; c < 8; c++) colsq[c] = 0.f;
#pragma unroll
    for (int r = 0; r < 8; r++) {
        int m = ty * 8 + r;
        float sc = (m < 64) ? qs[m] : ks[m - 64];
        float sh = (m < 64) ? qb[m] : kb[m - 64];
#pragma unroll
        for (int c = 0; c < 8; c++) {
            float v = fmaf(acc[r][c], sc, sh);
            acc[r][c] = v;
            colsq[c] += v * v;
        }
    }
#pragma unroll
    for (int c = 0; c < 8; c++) Ps[ty][tx * 8 + c] = colsq[c];
    __syncthreads();
    {
        int col = tid & 127, half = tid >> 7;
        float s = 0.f;
#pragma unroll
        for (int g = 0; g < 8; g++) s += Ps[half * 8 + g][col];
        Nn[half][col] = 1.f / fmaxf(sqrtf(s), 1e-12f);
    }
    __syncthreads();

    const int half = (ty >= 8) ? 1 : 0;
#pragma unroll
    for (int r = 0; r < 8; r++) {
        int m = ty * 8 + r;
        float* out = (m < 64) ? (g_qn + ((size_t)b * CQK + m) * HW)
                              : (g_kn + ((size_t)b * CQK + (m - 64)) * HW);
#pragma unroll
        for (int c = 0; c < 8; c++) {
            int col = tx * 8 + c;
            out[n0 + col] = acc[r][c] * Nn[half][col];
        }
    }
}

// ============================================================
// K2: v projection (256x256 GEMM) + BN + ReLU
// grid (HW/128, 2, B), block 256
// ============================================================
__global__ void k_v(const float* __restrict__ x,
                    const float* __restrict__ vW, const float* __restrict__ vs, const float* __restrict__ vb)
{
    __shared__ float Wt[128][16];
    __shared__ float Xt[16][128];

    const int b   = blockIdx.z;
    const int co0 = blockIdx.y * 128;
    const int n0  = blockIdx.x * 128;
    const int tid = threadIdx.x;
    const int ty = tid >> 4, tx = tid & 15;

    float acc[8][8];
#pragma unroll
    for (int r = 0; r < 8; r++)
#pragma unroll
        for (int c = 0; c < 8; c++) acc[r][c] = 0.f;

    const float* xb = x + (size_t)b * CIN * HW;

    for (int kk = 0; kk < CIN; kk += 16) {
#pragma unroll
        for (int i = 0; i < 8; i++) {
            int idx = i * 256 + tid;
            int m = idx >> 4, kl = idx & 15;
            Wt[m][kl] = vW[(size_t)(co0 + m) * CIN + kk + kl];
        }
#pragma unroll
        for (int i = 0; i < 8; i++) {
            int idx = i * 256 + tid;
            int r = idx >> 7, c = idx & 127;
            Xt[r][c] = xb[(size_t)(kk + r) * HW + n0 + c];
        }
        __syncthreads();
#pragma unroll
        for (int k = 0; k < 16; k++) {
            float wr[8], xr[8];
#pragma unroll
            for (int r = 0; r < 8; r++) wr[r] = Wt[ty * 8 + r][k];
#pragma unroll
            for (int c = 0; c < 8; c++) xr[c] = Xt[k][tx * 8 + c];
#pragma unroll
            for (int r = 0; r < 8; r++)
#pragma unroll
                for (int c = 0; c < 8; c++) acc[r][c] = fmaf(wr[r], xr[c], acc[r][c]);
        }
        __syncthreads();
    }

#pragma unroll
    for (int r = 0; r < 8; r++) {
        int co = co0 + ty * 8 + r;
        float sc = vs[co], sh = vb[co];
        float* out = g_v + ((size_t)b * CIN + co) * HW + n0;
#pragma unroll
        for (int c = 0; c < 8; c++)
            out[tx * 8 + c] = fmaxf(fmaf(acc[r][c], sc, sh), 0.f);
    }
}

// ============================================================
// K3: partial sim = kn @ v^T over a 512-pixel chunk (deterministic split-N)
// grid (NCH, B), block 256
// ============================================================
__global__ void k_sim()
{
    __shared__ float ksm[CQK][17];
    __shared__ float vsm[CIN][17];

    const int b  = blockIdx.y;
    const int ch = blockIdx.x;
    const int n0 = ch * PIX_PER_CHUNK;
    const int tid = threadIdx.x;
    const int l = tid & 31, g = tid >> 5;

    float acc[8][8];
#pragma unroll
    for (int i = 0; i < 8; i++)
#pragma unroll
        for (int j = 0; j < 8; j++) acc[i][j] = 0.f;

    const float* kb = g_kn + (size_t)b * CQK * HW;
    const float* vb = g_v + (size_t)b * CIN * HW;

    for (int p0 = 0; p0 < PIX_PER_CHUNK; p0 += 16) {
#pragma unroll
        for (int i = 0; i < 4; i++) {
            int idx = i * 256 + tid;
            int c = idx >> 4, p = idx & 15;
            ksm[c][p] = kb[(size_t)c * HW + n0 + p0 + p];
        }
#pragma unroll
        for (int i = 0; i < 16; i++) {
            int idx = i * 256 + tid;
            int c = idx >> 4, p = idx & 15;
            vsm[c][p] = vb[(size_t)c * HW + n0 + p0 + p];
        }
        __syncthreads();
#pragma unroll
        for (int p = 0; p < 16; p++) {
            float kr[8], vr[8];
#pragma unroll
            for (int i = 0; i < 8; i++) kr[i] = ksm[g + 8 * i][p];
#pragma unroll
            for (int j = 0; j < 8; j++) vr[j] = vsm[l + 32 * j][p];
#pragma unroll
            for (int i = 0; i < 8; i++)
#pragma unroll
                for (int j = 0; j < 8; j++) acc[i][j] = fmaf(kr[i], vr[j], acc[i][j]);
        }
        __syncthreads();
    }

    float* outp = g_simp + ((size_t)(b * NCH + ch) * CQK) * CIN;
#pragma unroll
    for (int i = 0; i < 8; i++)
#pragma unroll
        for (int j = 0; j < 8; j++)
            outp[(g + 8 * i) * CIN + l + 32 * j] = acc[i][j];
}

// K3b: reduce partials -> g_sim. grid 256, block 256
__global__ void k_simreduce()
{
    int o = blockIdx.x * 256 + threadIdx.x;   // [B][CQK][CIN]
    int b = o / (CQK * CIN);
    int cv = o - b * (CQK * CIN);
    float s = 0.f;
#pragma unroll 8
    for (int ch = 0; ch < NCH; ch++)
        s += g_simp[((size_t)(b * NCH + ch)) * CQK * CIN + cv];
    g_sim[o] = s;
}

// ============================================================
// K4a: M2[b][o][c] = sum_v oW[o][v] * sim[b][c][v]   (folds o-projection)
// grid (B*CQK), block 256
// ============================================================
__global__ void k_m2(const float* __restrict__ oW)
{
    __shared__ float ssm[CIN];
    const int b = blockIdx.x >> 6;
    const int c = blockIdx.x & 63;
    const int o = threadIdx.x;
    ssm[o] = g_sim[((size_t)b * CQK + c) * CIN + o];
    __syncthreads();
    float s = 0.f;
#pragma unroll 8
    for (int v = 0; v < CIN; v++) s = fmaf(oW[(size_t)o * CIN + v], ssm[v], s);
    g_M2[((size_t)b * CIN + o) * CQK + c] = s;
}

// ============================================================
// K4: fuse = relu(o_scale*(M2 @ qn) + o_shift) + x + bilinear_up(up_feat_in)
// grid (128 rows, 2 co-halves, B), block 256. One block = one image row.
// ============================================================
__global__ void k_ctx(const float* __restrict__ x, const float* __restrict__ up,
                      const float* __restrict__ os, const float* __restrict__ ob)
{
    __shared__ float Wt[128][8];
    __shared__ float Xt[8][128];
    __shared__ float upH[128][64];

    const int b   = blockIdx.z;
    const int co0 = blockIdx.y * 128;
    const int h   = blockIdx.x;
    const int n0  = h * Ww;
    const int tid = threadIdx.x;
    const int ty = tid >> 4, tx = tid & 15;

    // row-interpolated upsample line for this output row (half-pixel, clamped)
    {
        float shf = 0.5f * h - 0.25f;
        int h0 = (int)floorf(shf);
        float wh1 = shf - (float)h0;
        int h0c = h0 < 0 ? 0 : h0;
        int h1c = (h0 + 1) > 63 ? 63 : (h0 + 1);
        const float* ub = up + ((size_t)(b * CIN + co0)) * 64 * 64;
#pragma unroll
        for (int i = 0; i < 32; i++) {
            int idx = i * 256 + tid;
            int r = idx >> 6, sw = idx & 63;
            upH[r][sw] = (1.f - wh1) * ub[(r * 64 + h0c) * 64 + sw]
                       + wh1 * ub[(r * 64 + h1c) * 64 + sw];
        }
    }

    float acc[8][8];
#pragma unroll
    for (int r = 0; r < 8; r++)
#pragma unroll
        for (int c = 0; c < 8; c++) acc[r][c] = 0.f;

    const float* qb = g_qn + (size_t)b * CQK * HW;
    const float* Mb = g_M2 + (size_t)b * CIN * CQK;

    for (int kk = 0; kk < CQK; kk += 8) {
#pragma unroll
        for (int i = 0; i < 4; i++) {
            int idx = i * 256 + tid;
            int m = idx >> 3, kl = idx & 7;
            Wt[m][kl] = Mb[(size_t)(co0 + m) * CQK + kk + kl];
        }
#pragma unroll
        for (int i = 0; i < 4; i++) {
            int idx = i * 256 + tid;
            int r = idx >> 7, c = idx & 127;
            Xt[r][c] = qb[(size_t)(kk + r) * HW + n0 + c];
        }
        __syncthreads();
#pragma unroll
        for (int k = 0; k < 8; k++) {
            float wr[8], xr[8];
#pragma unroll
            for (int r = 0; r < 8; r++) wr[r] = Wt[ty * 8 + r][k];
#pragma unroll
            for (int c = 0; c < 8; c++) xr[c] = Xt[k][tx * 8 + c];
#pragma unroll
            for (int r = 0; r < 8; r++)
#pragma unroll
                for (int c = 0; c < 8; c++) acc[r][c] = fmaf(wr[r], xr[c], acc[r][c]);
        }
        __syncthreads();
    }

    // epilogue: BN + ReLU + residual + upsample-add
    float ww1a[8];
    int w0c[8], w1c[8];
#pragma unroll
    for (int c = 0; c < 8; c++) {
        int w = tx * 8 + c;
        float swf = 0.5f * w - 0.25f;
        int w0 = (int)floorf(swf);
        ww1a[c] = swf - (float)w0;
        w0c[c] = w0 < 0 ? 0 : w0;
        w1c[c] = (w0 + 1) > 63 ? 63 : (w0 + 1);
    }
    const float* xb = x + ((size_t)b * CIN + co0) * HW;
    float* fb = g_fuse + ((size_t)b * CIN + co0) * HW;
#pragma unroll
    for (int r = 0; r < 8; r++) {
        int m = ty * 8 + r;
        int co = co0 + m;
        float sc = os[co], sh = ob[co];
#pragma unroll
        for (int c = 0; c < 8; c++) {
            int w = tx * 8 + c;
            float y = fmaxf(fmaf(acc[r][c], sc, sh), 0.f);
            float uv = (1.f - ww1a[c]) * upH[m][w0c[c]] + ww1a[c] * upH[m][w1c[c]];
            fb[(size_t)m * HW + n0 + w] = y + xb[(size_t)m * HW + n0 + w] + uv;
        }
    }
}

// ============================================================
// K5: 3x3 conv (256 -> 128) + BN + ReLU, direct, register-tiled
// grid (8 wtiles, 8 htiles, B*4 co-blocks), block 256
// ============================================================
__global__ void k_conv(const float* __restrict__ sW, const float* __restrict__ ss,
                       const float* __restrict__ sb, float* __restrict__ out)
{
    __shared__ __align__(16) float ism[16][18][18];
    __shared__ __align__(16) float wsm[16][9][32];

    const int z = blockIdx.z;
    const int b = z >> 2;
    const int co0 = (z & 3) * 32;
    const int h0 = blockIdx.y * 16, w0 = blockIdx.x * 16;
    const int tid = threadIdx.x;
    const int tco = tid >> 5;          // 0..7  (4 output channels each)
    const int tpx = tid & 31;
    const int ph  = tpx >> 1;          // 0..15
    const int pwb = (tpx & 1) * 8;     // 0 or 8

    float acc[4][8];
#pragma unroll
    for (int o = 0; o < 4; o++)
#pragma unroll
        for (int j = 0; j < 8; j++) acc[o][j] = 0.f;

    const float* fb = g_fuse + (size_t)b * CIN * HW;

    for (int ci0 = 0; ci0 < CIN; ci0 += 16) {
        for (int idx = tid; idx < 16 * 18 * 18; idx += 256) {
            int ci = idx / 324;
            int rem = idx - ci * 324;
            int lh = rem / 18, lw = rem - lh * 18;
            int gh = h0 - 1 + lh, gw = w0 - 1 + lw;
            float v = 0.f;
            if (gh >= 0 && gh < Hh && gw >= 0 && gw < Ww)
                v = fb[(size_t)(ci0 + ci) * HW + gh * Ww + gw];
            ism[ci][lh][lw] = v;
        }
        for (int idx = tid; idx < 16 * 9 * 32; idx += 256) {
            int col = idx / 144;
            int rem = idx - col * 144;
            int ci = rem / 9, tap = rem - ci * 9;
            wsm[ci][tap][col] = sW[((size_t)(co0 + col) * CIN + ci0 + ci) * 9 + tap];
        }
        __syncthreads();

#pragma unroll
        for (int ci = 0; ci < 16; ci++) {
#pragma unroll
            for (int kh = 0; kh < 3; kh++) {
                float inr[10];
#pragma unroll
                for (int j = 0; j < 10; j++) inr[j] = ism[ci][ph + kh][pwb + j];
#pragma unroll
                for (int kw = 0; kw < 3; kw++) {
                    const float4 wv = *reinterpret_cast<const float4*>(&wsm[ci][kh * 3 + kw][tco * 4]);
#pragma unroll
                    for (int j = 0; j < 8; j++) {
                        acc[0][j] = fmaf(wv.x, inr[kw + j], acc[0][j]);
                        acc[1][j] = fmaf(wv.y, inr[kw + j], acc[1][j]);
                        acc[2][j] = fmaf(wv.z, inr[kw + j], acc[2][j]);
                        acc[3][j] = fmaf(wv.w, inr[kw + j], acc[3][j]);
                    }
                }
            }
        }
        __syncthreads();
    }

#pragma unroll
    for (int o = 0; o < 4; o++) {
        int co = co0 + tco * 4 + o;
        float sc = ss[co], sh = sb[co];
        float* op = out + (((size_t)b * CS + co) * Hh + h0 + ph) * Ww + w0 + pwb;
#pragma unroll
        for (int j = 0; j < 8; j++)
            op[j] = fmaxf(fmaf(acc[o][j], sc, sh), 0.f);
    }
}

// ============================================================
extern "C" void kernel_launch(void* const* d_in, const int* in_sizes, int n_in,
                              void* d_out, int out_size)
{
    (void)in_sizes; (void)n_in; (void)out_size;
    const float* x        = (const float*)d_in[0];
    const float* up       = (const float*)d_in[1];
    const float* qW       = (const float*)d_in[2];
    const float* q_scale  = (const float*)d_in[3];
    const float* q_shift  = (const float*)d_in[4];
    const float* kW       = (const float*)d_in[5];
    const float* k_scale  = (const float*)d_in[6];
    const float* k_shift  = (const float*)d_in[7];
    const float* vW       = (const float*)d_in[8];
    const float* v_scale  = (const float*)d_in[9];
    const float* v_shift  = (const float*)d_in[10];
    const float* oW       = (const float*)d_in[11];
    const float* o_scale  = (const float*)d_in[12];
    const float* o_shift  = (const float*)d_in[13];
    const float* sW       = (const float*)d_in[14];
    const float* s_scale  = (const float*)d_in[15];
    const float* s_shift  = (const float*)d_in[16];
    float* out = (float*)d_out;

    k_qk<<<dim3(HW / 128, Bn), 256>>>(x, qW, q_scale, q_shift, kW, k_scale, k_shift);
    k_v<<<dim3(HW / 128, 2, Bn), 256>>>(x, vW, v_scale, v_shift);
    k_sim<<<dim3(NCH, Bn), 256>>>();
    k_simreduce<<<256, 256>>>();
    k_m2<<<Bn * CQK, 256>>>(oW);
    k_ctx<<<dim3(Hh, 2, Bn), 256>>>(x, up, o_scale, o_shift);
    k_conv<<<dim3(8, 8, Bn * 4), 256>>>(sW, s_scale, s_shift, out);
}

// round 2
// speedup vs baseline: 2.2896x; 2.2896x over previous
#include <cuda_runtime.h>
#include <math.h>
#include <stdint.h>

#define Bn   4
#define CIN  256
#define CQK  64
#define CS   128
#define Hh   128
#define Ww   128
#define HW   (Hh*Ww)
#define NCH  32
#define PIX_PER_CHUNK (HW/NCH)     // 512

// ---- scratch ----
__device__ float g_qn  [Bn*CQK*HW];
__device__ float g_kn  [Bn*CQK*HW];
__device__ float g_v   [Bn*CIN*HW];
__device__ float g_fuse[Bn*CIN*HW];
__device__ float g_simp[Bn*NCH*CQK*CIN];
__device__ float g_sim [Bn*CQK*CIN];
__device__ float g_M2  [Bn*CIN*CQK];

// packed tf32 weights (fragment-friendly: [(kb*M+m)*4+kk] -> {k=kb*8+kk, k=kb*8+4+kk})
__device__ uint2 g_Aqk[16384];    // M=128 (q,k stacked), K=256
__device__ uint2 g_Av [32768];    // M=256, K=256
__device__ uint2 g_wp2[147456];   // conv: [dh][ch][tap][(kb*128+co)*4+kk]

__device__ __forceinline__ uint32_t f2tf(float f) {
    uint32_t u; asm("cvt.rna.tf32.f32 %0, %1;" : "=r"(u) : "f"(f)); return u;
}

__device__ __forceinline__ void mma8(float* c, uint2 a01, uint2 a13, uint2 b) {
    asm volatile(
        "mma.sync.aligned.m16n8k8.row.col.f32.tf32.tf32.f32 "
        "{%0,%1,%2,%3}, {%4,%5,%6,%7}, {%8,%9}, {%0,%1,%2,%3};"
        : "+f"(c[0]), "+f"(c[1]), "+f"(c[2]), "+f"(c[3])
        : "r"(a01.x), "r"(a13.x), "r"(a01.y), "r"(a13.y), "r"(b.x), "r"(b.y));
}

// ============ weight pack kernels (run each launch; deterministic) ============
__global__ void k_pack_qk(const float* __restrict__ qW, const float* __restrict__ kW)
{
    int idx = blockIdx.x * 256 + threadIdx.x;          // < 16384
    int kk = idx & 3, m = (idx >> 2) & 127, kb = idx >> 9;
    int k0 = kb * 8 + kk;
    const float* wr = (m < 64) ? (qW + (size_t)m * CIN) : (kW + (size_t)(m - 64) * CIN);
    g_Aqk[idx] = make_uint2(f2tf(wr[k0]), f2tf(wr[k0 + 4]));
}

__global__ void k_pack_v(const float* __restrict__ vW)
{
    int idx = blockIdx.x * 256 + threadIdx.x;          // < 32768
    int kk = idx & 3, m = (idx >> 2) & 255, kb = idx >> 10;
    int k0 = kb * 8 + kk;
    const float* wr = vW + (size_t)m * CIN;
    g_Av[idx] = make_uint2(f2tf(wr[k0]), f2tf(wr[k0 + 4]));
}

__global__ void k_pack_conv(const float* __restrict__ sW)
{
    int idx = blockIdx.x * 256 + threadIdx.x;          // < 147456
    int r = idx & 1023, s = idx >> 10;
    int kk = r & 3, co = (r >> 2) & 127, kb = r >> 9;
    int tap = s % 3, t2 = s / 3, ch = t2 & 15, dh = t2 >> 4;
    int ci = ch * 16 + kb * 8 + kk;
    float w0 = sW[((size_t)co * CIN + ci) * 9 + dh * 3 + tap];
    float w1 = sW[((size_t)co * CIN + ci + 4) * 9 + dh * 3 + tap];
    g_wp2[idx] = make_uint2(f2tf(w0), f2tf(w1));
}

// ============ K1: q,k projections + BN + per-pixel L2 norm (tf32 mma) ============
__global__ void k_qk_mma(const float* __restrict__ x,
                         const float* __restrict__ qs, const float* __restrict__ qb,
                         const float* __restrict__ kscale, const float* __restrict__ kshift)
{
    __shared__ uint2 Asm[2048];       // 4kb x 128m x 4kk
    __shared__ uint2 Bsm[16 * 132];   // 16 kkb x 132 n (padded)
    __shared__ float Sq[4][128];
    __shared__ float Nn[2][128];

    const int b = blockIdx.y, n0 = blockIdx.x * 128;
    const int tid = threadIdx.x, lane = tid & 31, w = tid >> 5;
    const int g = lane >> 2, kk = lane & 3;
    const int mg = w >> 1, ng = w & 1;
    const int m0w = mg * 32, n0w = ng * 64;

    float acc[2][8][4];
#pragma unroll
    for (int mt = 0; mt < 2; mt++)
#pragma unroll
        for (int nt = 0; nt < 8; nt++)
#pragma unroll
            for (int i = 0; i < 4; i++) acc[mt][nt][i] = 0.f;

    const float* xb = x + (size_t)b * CIN * HW;

    for (int it = 0; it < 8; it++) {
#pragma unroll
        for (int j = tid; j < 2048; j += 256) Asm[j] = g_Aqk[it * 2048 + j];
#pragma unroll
        for (int j = tid; j < 2048; j += 256) {
            int n = j & 127, kkb = j >> 7;
            int k0 = it * 32 + (kkb >> 2) * 8 + (kkb & 3);
            Bsm[kkb * 132 + n] = make_uint2(f2tf(xb[(size_t)k0 * HW + n0 + n]),
                                            f2tf(xb[(size_t)(k0 + 4) * HW + n0 + n]));
        }
        __syncthreads();
#pragma unroll
        for (int kb = 0; kb < 4; kb++) {
            uint2 a01[2], a13[2];
#pragma unroll
            for (int mt = 0; mt < 2; mt++) {
                a01[mt] = Asm[(kb * 128 + m0w + mt * 16 + g) * 4 + kk];
                a13[mt] = Asm[(kb * 128 + m0w + mt * 16 + 8 + g) * 4 + kk];
            }
#pragma unroll
            for (int nt = 0; nt < 8; nt++) {
                uint2 bb = Bsm[(kb * 4 + kk) * 132 + n0w + nt * 8 + g];
                mma8(acc[0][nt], a01[0], a13[0], bb);
                mma8(acc[1][nt], a01[1], a13[1], bb);
            }
        }
        __syncthreads();
    }

    // BN + column sums of squares
    float sq[8][2];
#pragma unroll
    for (int nt = 0; nt < 8; nt++) { sq[nt][0] = 0.f; sq[nt][1] = 0.f; }
#pragma unroll
    for (int mt = 0; mt < 2; mt++) {
        int r0 = m0w + mt * 16 + g, r1 = r0 + 8;
        bool isq = (r0 < 64);
        float sc0 = isq ? qs[r0] : kscale[r0 - 64];
        float sh0 = isq ? qb[r0] : kshift[r0 - 64];
        float sc1 = isq ? qs[r1] : kscale[r1 - 64];
        float sh1 = isq ? qb[r1] : kshift[r1 - 64];
#pragma unroll
        for (int nt = 0; nt < 8; nt++) {
            float v0 = fmaf(acc[mt][nt][0], sc0, sh0);
            float v1 = fmaf(acc[mt][nt][1], sc0, sh0);
            float v2 = fmaf(acc[mt][nt][2], sc1, sh1);
            float v3 = fmaf(acc[mt][nt][3], sc1, sh1);
            acc[mt][nt][0] = v0; acc[mt][nt][1] = v1;
            acc[mt][nt][2] = v2; acc[mt][nt][3] = v3;
            sq[nt][0] += v0 * v0 + v2 * v2;
            sq[nt][1] += v1 * v1 + v3 * v3;
        }
    }
#pragma unroll
    for (int nt = 0; nt < 8; nt++) {
#pragma unroll
        for (int o = 4; o < 32; o <<= 1) {
            sq[nt][0] += __shfl_xor_sync(0xffffffffu, sq[nt][0], o);
            sq[nt][1] += __shfl_xor_sync(0xffffffffu, sq[nt][1], o);
        }
    }
    if (lane < 4) {
#pragma unroll
        for (int nt = 0; nt < 8; nt++) {
            int c = n0w + nt * 8 + lane * 2;
            Sq[mg][c] = sq[nt][0];
            Sq[mg][c + 1] = sq[nt][1];
        }
    }
    __syncthreads();
    {
        int col = tid & 127, half = tid >> 7;
        float s = Sq[half * 2][col] + Sq[half * 2 + 1][col];
        Nn[half][col] = 1.f / fmaxf(sqrtf(s), 1e-12f);
    }
    __syncthreads();

    const int halfW = (mg >= 2) ? 1 : 0;
    float* outb = halfW ? (g_kn + (size_t)b * CQK * HW) : (g_qn + (size_t)b * CQK * HW);
#pragma unroll
    for (int mt = 0; mt < 2; mt++) {
        int r = m0w + mt * 16 + g - halfW * 64;
#pragma unroll
        for (int nt = 0; nt < 8; nt++) {
            int c = n0w + nt * 8 + (lane & 3) * 2;
            float i0 = Nn[halfW][c], i1 = Nn[halfW][c + 1];
            float2 o0 = make_float2(acc[mt][nt][0] * i0, acc[mt][nt][1] * i1);
            float2 o1 = make_float2(acc[mt][nt][2] * i0, acc[mt][nt][3] * i1);
            *(float2*)&outb[(size_t)r * HW + n0 + c] = o0;
            *(float2*)&outb[(size_t)(r + 8) * HW + n0 + c] = o1;
        }
    }
}

// ============ K2: v projection + BN + ReLU (tf32 mma) ============
__global__ void k_v_mma(const float* __restrict__ x,
                        const float* __restrict__ vs, const float* __restrict__ vb)
{
    __shared__ uint2 Asm[2048];
    __shared__ uint2 Bsm[16 * 132];

    const int b = blockIdx.z, co0 = blockIdx.y * 128, n0 = blockIdx.x * 128;
    const int tid = threadIdx.x, lane = tid & 31, w = tid >> 5;
    const int g = lane >> 2, kk = lane & 3;
    const int mg = w >> 1, ng = w & 1;
    const int m0w = mg * 32, n0w = ng * 64;

    float acc[2][8][4];
#pragma unroll
    for (int mt = 0; mt < 2; mt++)
#pragma unroll
        for (int nt = 0; nt < 8; nt++)
#pragma unroll
            for (int i = 0; i < 4; i++) acc[mt][nt][i] = 0.f;

    const float* xb = x + (size_t)b * CIN * HW;

    for (int it = 0; it < 8; it++) {
#pragma unroll
        for (int j = tid; j < 2048; j += 256) {
            int kb_l = j >> 9, r = j & 511;
            Asm[j] = g_Av[(size_t)(it * 4 + kb_l) * 1024 + co0 * 4 + r];
        }
#pragma unroll
        for (int j = tid; j < 2048; j += 256) {
            int n = j & 127, kkb = j >> 7;
            int k0 = it * 32 + (kkb >> 2) * 8 + (kkb & 3);
            Bsm[kkb * 132 + n] = make_uint2(f2tf(xb[(size_t)k0 * HW + n0 + n]),
                                            f2tf(xb[(size_t)(k0 + 4) * HW + n0 + n]));
        }
        __syncthreads();
#pragma unroll
        for (int kb = 0; kb < 4; kb++) {
            uint2 a01[2], a13[2];
#pragma unroll
            for (int mt = 0; mt < 2; mt++) {
                a01[mt] = Asm[(kb * 128 + m0w + mt * 16 + g) * 4 + kk];
                a13[mt] = Asm[(kb * 128 + m0w + mt * 16 + 8 + g) * 4 + kk];
            }
#pragma unroll
            for (int nt = 0; nt < 8; nt++) {
                uint2 bb = Bsm[(kb * 4 + kk) * 132 + n0w + nt * 8 + g];
                mma8(acc[0][nt], a01[0], a13[0], bb);
                mma8(acc[1][nt], a01[1], a13[1], bb);
            }
        }
        __syncthreads();
    }

#pragma unroll
    for (int mt = 0; mt < 2; mt++) {
        int co = co0 + m0w + mt * 16 + g;
        float sc0 = vs[co], sh0 = vb[co];
        float sc1 = vs[co + 8], sh1 = vb[co + 8];
        float* o0p = g_v + ((size_t)b * CIN + co) * HW + n0;
        float* o1p = g_v + ((size_t)b * CIN + co + 8) * HW + n0;
#pragma unroll
        for (int nt = 0; nt < 8; nt++) {
            int c = n0w + nt * 8 + (lane & 3) * 2;
            float2 o0 = make_float2(fmaxf(fmaf(acc[mt][nt][0], sc0, sh0), 0.f),
                                    fmaxf(fmaf(acc[mt][nt][1], sc0, sh0), 0.f));
            float2 o1 = make_float2(fmaxf(fmaf(acc[mt][nt][2], sc1, sh1), 0.f),
                                    fmaxf(fmaf(acc[mt][nt][3], sc1, sh1), 0.f));
            *(float2*)&o0p[c] = o0;
            *(float2*)&o1p[c] = o1;
        }
    }
}

// ============ K3: partial sim = kn @ v^T (tf32 mma, deterministic split-N) ============
__global__ void k_sim_mma()
{
    __shared__ uint2 Asm[1024];        // 4kb x 64m x 4kk
    __shared__ uint2 Bsm[256 * 18];    // n-major, 16 used + 2 pad per n

    const int b = blockIdx.y, ch = blockIdx.x;
    const int p0 = ch * PIX_PER_CHUNK;
    const int tid = threadIdx.x, lane = tid & 31, w = tid >> 5;
    const int g = lane >> 2, kk = lane & 3;
    const int mg = w >> 2, ng = w & 3;
    const int m0w = mg * 32, n0w = ng * 64;

    float acc[2][8][4];
#pragma unroll
    for (int mt = 0; mt < 2; mt++)
#pragma unroll
        for (int nt = 0; nt < 8; nt++)
#pragma unroll
            for (int i = 0; i < 4; i++) acc[mt][nt][i] = 0.f;

    const float* kbp = g_kn + (size_t)b * CQK * HW + p0;
    const float* vbp = g_v + (size_t)b * CIN * HW + p0;

    for (int it = 0; it < 16; it++) {
        int pk = it * 32;
#pragma unroll
        for (int j = tid; j < 1024; j += 256) {
            int m = j >> 4, kkb = j & 15;
            int k = pk + (kkb >> 2) * 8 + (kkb & 3);
            Asm[((kkb >> 2) * 64 + m) * 4 + (kkb & 3)] =
                make_uint2(f2tf(kbp[(size_t)m * HW + k]), f2tf(kbp[(size_t)m * HW + k + 4]));
        }
#pragma unroll
        for (int j = tid; j < 4096; j += 256) {
            int n = j >> 4, kkb = j & 15;
            int k = pk + (kkb >> 2) * 8 + (kkb & 3);
            Bsm[n * 18 + kkb] =
                make_uint2(f2tf(vbp[(size_t)n * HW + k]), f2tf(vbp[(size_t)n * HW + k + 4]));
        }
        __syncthreads();
#pragma unroll
        for (int kb = 0; kb < 4; kb++) {
            uint2 a01[2], a13[2];
#pragma unroll
            for (int mt = 0; mt < 2; mt++) {
                a01[mt] = Asm[(kb * 64 + m0w + mt * 16 + g) * 4 + kk];
                a13[mt] = Asm[(kb * 64 + m0w + mt * 16 + 8 + g) * 4 + kk];
            }
#pragma unroll
            for (int nt = 0; nt < 8; nt++) {
                uint2 bb = Bsm[(n0w + nt * 8 + g) * 18 + kb * 4 + kk];
                mma8(acc[0][nt], a01[0], a13[0], bb);
                mma8(acc[1][nt], a01[1], a13[1], bb);
            }
        }
        __syncthreads();
    }

    float* outp = g_simp + (size_t)(b * NCH + ch) * CQK * CIN;
#pragma unroll
    for (int mt = 0; mt < 2; mt++) {
        int r = m0w + mt * 16 + g;
#pragma unroll
        for (int nt = 0; nt < 8; nt++) {
            int c = n0w + nt * 8 + (lane & 3) * 2;
            *(float2*)&outp[(size_t)r * CIN + c] = make_float2(acc[mt][nt][0], acc[mt][nt][1]);
            *(float2*)&outp[(size_t)(r + 8) * CIN + c] = make_float2(acc[mt][nt][2], acc[mt][nt][3]);
        }
    }
}

// K3b: reduce partials
__global__ void k_simreduce()
{
    int o = blockIdx.x * 256 + threadIdx.x;
    int b = o / (CQK * CIN);
    int cv = o - b * (CQK * CIN);
    float s = 0.f;
#pragma unroll 8
    for (int ch = 0; ch < NCH; ch++)
        s += g_simp[((size_t)(b * NCH + ch)) * CQK * CIN + cv];
    g_sim[o] = s;
}

// K4a: M2 = oW @ sim^T
__global__ void k_m2(const float* __restrict__ oW)
{
    __shared__ float ssm[CIN];
    const int b = blockIdx.x >> 6;
    const int c = blockIdx.x & 63;
    const int o = threadIdx.x;
    ssm[o] = g_sim[((size_t)b * CQK + c) * CIN + o];
    __syncthreads();
    float s = 0.f;
#pragma unroll 8
    for (int v = 0; v < CIN; v++) s = fmaf(oW[(size_t)o * CIN + v], ssm[v], s);
    g_M2[((size_t)b * CIN + o) * CQK + c] = s;
}

// K4: fuse = relu(BN(M2 @ qn)) + x + bilinear_up  (fp32, small K=64)
__global__ void k_ctx(const float* __restrict__ x, const float* __restrict__ up,
                      const float* __restrict__ os, const float* __restrict__ ob)
{
    __shared__ float Wt[128][8];
    __shared__ float Xt[8][128];
    __shared__ float upH[128][64];

    const int b = blockIdx.z;
    const int co0 = blockIdx.y * 128;
    const int h = blockIdx.x;
    const int n0 = h * Ww;
    const int tid = threadIdx.x;
    const int ty = tid >> 4, tx = tid & 15;

    {
        float shf = 0.5f * h - 0.25f;
        int h0 = (int)floorf(shf);
        float wh1 = shf - (float)h0;
        int h0c = h0 < 0 ? 0 : h0;
        int h1c = (h0 + 1) > 63 ? 63 : (h0 + 1);
        const float* ub = up + ((size_t)(b * CIN + co0)) * 64 * 64;
#pragma unroll
        for (int i = 0; i < 32; i++) {
            int idx = i * 256 + tid;
            int r = idx >> 6, sw = idx & 63;
            upH[r][sw] = (1.f - wh1) * ub[(r * 64 + h0c) * 64 + sw]
                       + wh1 * ub[(r * 64 + h1c) * 64 + sw];
        }
    }

    float acc[8][8];
#pragma unroll
    for (int r = 0; r < 8; r++)
#pragma unroll
        for (int c = 0; c < 8; c++) acc[r][c] = 0.f;

    const float* qb = g_qn + (size_t)b * CQK * HW;
    const float* Mb = g_M2 + (size_t)b * CIN * CQK;

    for (int kk = 0; kk < CQK; kk += 8) {
#pragma unroll
        for (int i = 0; i < 4; i++) {
            int idx = i * 256 + tid;
            int m = idx >> 3, kl = idx & 7;
            Wt[m][kl] = Mb[(size_t)(co0 + m) * CQK + kk + kl];
        }
#pragma unroll
        for (int i = 0; i < 4; i++) {
            int idx = i * 256 + tid;
            int r = idx >> 7, c = idx & 127;
            Xt[r][c] = qb[(size_t)(kk + r) * HW + n0 + c];
        }
        __syncthreads();
#pragma unroll
        for (int k = 0; k < 8; k++) {
            float wr[8], xr[8];
#pragma unroll
            for (int r = 0; r < 8; r++) wr[r] = Wt[ty * 8 + r][k];
#pragma unroll
            for (int c = 0; c < 8; c++) xr[c] = Xt[k][tx * 8 + c];
#pragma unroll
            for (int r = 0; r < 8; r++)
#pragma unroll
                for (int c = 0; c < 8; c++) acc[r][c] = fmaf(wr[r], xr[c], acc[r][c]);
        }
        __syncthreads();
    }

    float ww1a[8];
    int w0c[8], w1c[8];
#pragma unroll
    for (int c = 0; c < 8; c++) {
        int w = tx * 8 + c;
        float swf = 0.5f * w - 0.25f;
        int w0 = (int)floorf(swf);
        ww1a[c] = swf - (float)w0;
        w0c[c] = w0 < 0 ? 0 : w0;
        w1c[c] = (w0 + 1) > 63 ? 63 : (w0 + 1);
    }
    const float* xb = x + ((size_t)b * CIN + co0) * HW;
    float* fb = g_fuse + ((size_t)b * CIN + co0) * HW;
#pragma unroll
    for (int r = 0; r < 8; r++) {
        int m = ty * 8 + r;
        int co = co0 + m;
        float sc = os[co], sh = ob[co];
#pragma unroll
        for (int c = 0; c < 8; c++) {
            int w = tx * 8 + c;
            float y = fmaxf(fmaf(acc[r][c], sc, sh), 0.f);
            float uv = (1.f - ww1a[c]) * upH[m][w0c[c]] + ww1a[c] * upH[m][w1c[c]];
            fb[(size_t)m * HW + n0 + w] = y + xb[(size_t)m * HW + n0 + w] + uv;
        }
    }
}

// ============ K5: 3x3 conv as 9 shifted row-GEMMs (tf32 mma) ============
__global__ void k_conv_mma(const float* __restrict__ ss, const float* __restrict__ sb,
                           float* __restrict__ out)
{
    __shared__ uint2 Asm[3 * 1024];   // 3 taps x (2kb x 128co x 4kk)
    __shared__ uint2 Bsm[8 * 134];    // 8 kkb x 134 n (130 used, cols padded +-1)

    const int h = blockIdx.x, b = blockIdx.y;
    const int tid = threadIdx.x, lane = tid & 31, w = tid >> 5;
    const int g = lane >> 2, kk = lane & 3;
    const int mg = w >> 1, ng = w & 1;
    const int m0w = mg * 32, n0w = ng * 64;

    float acc[2][8][4];
#pragma unroll
    for (int mt = 0; mt < 2; mt++)
#pragma unroll
        for (int nt = 0; nt < 8; nt++)
#pragma unroll
            for (int i = 0; i < 4; i++) acc[mt][nt][i] = 0.f;

    const float* fbase = g_fuse + (size_t)b * CIN * HW;

    for (int dh = 0; dh < 3; dh++) {
        int hs = h + dh - 1;
        bool inb = (hs >= 0) && (hs < Hh);
        const float* fr = fbase + (size_t)hs * Ww;
        for (int ch = 0; ch < 16; ch++) {
#pragma unroll
            for (int j = tid; j < 3072; j += 256)
                Asm[j] = g_wp2[(size_t)(dh * 48 + ch * 3) * 1024 + j];
#pragma unroll
            for (int j = tid; j < 1040; j += 256) {
                int n = j % 130, kkb = j / 130;
                int ci = ch * 16 + (kkb >> 2) * 8 + (kkb & 3);
                int wx = n - 1;
                float v0 = 0.f, v1 = 0.f;
                if (inb && wx >= 0 && wx < Ww) {
                    v0 = fr[(size_t)ci * HW + wx];
                    v1 = fr[(size_t)(ci + 4) * HW + wx];
                }
                Bsm[kkb * 134 + n] = make_uint2(f2tf(v0), f2tf(v1));
            }
            __syncthreads();
#pragma unroll
            for (int tap = 0; tap < 3; tap++) {
#pragma unroll
                for (int kb = 0; kb < 2; kb++) {
                    uint2 a01[2], a13[2];
#pragma unroll
                    for (int mt = 0; mt < 2; mt++) {
                        a01[mt] = Asm[tap * 1024 + (kb * 128 + m0w + mt * 16 + g) * 4 + kk];
                        a13[mt] = Asm[tap * 1024 + (kb * 128 + m0w + mt * 16 + 8 + g) * 4 + kk];
                    }
#pragma unroll
                    for (int nt = 0; nt < 8; nt++) {
                        uint2 bb = Bsm[(kb * 4 + kk) * 134 + n0w + nt * 8 + g + tap];
                        mma8(acc[0][nt], a01[0], a13[0], bb);
                        mma8(acc[1][nt], a01[1], a13[1], bb);
                    }
                }
            }
            __syncthreads();
        }
    }

#pragma unroll
    for (int mt = 0; mt < 2; mt++) {
        int co = m0w + mt * 16 + g;
        float sc0 = ss[co], sh0 = sb[co];
        float sc1 = ss[co + 8], sh1 = sb[co + 8];
        float* o0p = out + ((size_t)b * CS + co) * HW + h * Ww;
        float* o1p = out + ((size_t)b * CS + co + 8) * HW + h * Ww;
#pragma unroll
        for (int nt = 0; nt < 8; nt++) {
            int c = n0w + nt * 8 + (lane & 3) * 2;
            float2 o0 = make_float2(fmaxf(fmaf(acc[mt][nt][0], sc0, sh0), 0.f),
                                    fmaxf(fmaf(acc[mt][nt][1], sc0, sh0), 0.f));
            float2 o1 = make_float2(fmaxf(fmaf(acc[mt][nt][2], sc1, sh1), 0.f),
                                    fmaxf(fmaf(acc[mt][nt][3], sc1, sh1), 0.f));
            *(float2*)&o0p[c] = o0;
            *(float2*)&o1p[c] = o1;
        }
    }
}

// ============================================================
extern "C" void kernel_launch(void* const* d_in, const int* in_sizes, int n_in,
                              void* d_out, int out_size)
{
    (void)in_sizes; (void)n_in; (void)out_size;
    const float* x        = (const float*)d_in[0];
    const float* up       = (const float*)d_in[1];
    const float* qW       = (const float*)d_in[2];
    const float* q_scale  = (const float*)d_in[3];
    const float* q_shift  = (const float*)d_in[4];
    const float* kW       = (const float*)d_in[5];
    const float* k_scale  = (const float*)d_in[6];
    const float* k_shift  = (const float*)d_in[7];
    const float* vW       = (const float*)d_in[8];
    const float* v_scale  = (const float*)d_in[9];
    const float* v_shift  = (const float*)d_in[10];
    const float* oW       = (const float*)d_in[11];
    const float* o_scale  = (const float*)d_in[12];
    const float* o_shift  = (const float*)d_in[13];
    const float* sW       = (const float*)d_in[14];
    const float* s_scale  = (const float*)d_in[15];
    const float* s_shift  = (const float*)d_in[16];
    float* out = (float*)d_out;

    k_pack_qk<<<64, 256>>>(qW, kW);
    k_pack_v<<<128, 256>>>(vW);
    k_pack_conv<<<576, 256>>>(sW);
    k_qk_mma<<<dim3(HW / 128, Bn), 256>>>(x, q_scale, q_shift, k_scale, k_shift);
    k_v_mma<<<dim3(HW / 128, 2, Bn), 256>>>(x, v_scale, v_shift);
    k_sim_mma<<<dim3(NCH, Bn), 256>>>();
    k_simreduce<<<256, 256>>>();
    k_m2<<<Bn * CQK, 256>>>(oW);
    k_ctx<<<dim3(Hh, 2, Bn), 256>>>(x, up, o_scale, o_shift);
    k_conv_mma<<<dim3(Hh, Bn), 256>>>(s_scale, s_shift, out);
}

// round 3
// speedup vs baseline: 2.8208x; 1.2320x over previous
#include <cuda_runtime.h>
#include <math.h>
#include <stdint.h>

#define Bn   4
#define CIN  256
#define CQK  64
#define CS   128
#define Hh   128
#define Ww   128
#define HW   (Hh*Ww)
#define NCH  32
#define PIX_PER_CHUNK (HW/NCH)     // 512

// ---- scratch ----
__device__ float g_qn  [Bn*CQK*HW];
__device__ float g_kn  [Bn*CQK*HW];
__device__ float g_v   [Bn*CIN*HW];
__device__ float g_fuse[Bn*CIN*HW];
__device__ float g_simp[Bn*NCH*CQK*CIN];
__device__ float g_sim [Bn*CQK*CIN];
__device__ float g_M2  [Bn*CIN*CQK];

// packed tf32 weights
__device__ uint2 g_Aqk[16384];    // M=128 (q,k stacked), K=256
__device__ uint2 g_Av [32768];    // M=256, K=256
__device__ uint2 g_wp2[147456];   // conv: [dh][ch][tap][(kb*128+co)*4+kk]

__device__ __forceinline__ uint32_t f2tf(float f) {
    uint32_t u; asm("cvt.rna.tf32.f32 %0, %1;" : "=r"(u) : "f"(f)); return u;
}

__device__ __forceinline__ void mma8(float* c, uint2 a01, uint2 a13, uint2 b) {
    asm volatile(
        "mma.sync.aligned.m16n8k8.row.col.f32.tf32.tf32.f32 "
        "{%0,%1,%2,%3}, {%4,%5,%6,%7}, {%8,%9}, {%0,%1,%2,%3};"
        : "+f"(c[0]), "+f"(c[1]), "+f"(c[2]), "+f"(c[3])
        : "r"(a01.x), "r"(a13.x), "r"(a01.y), "r"(a13.y), "r"(b.x), "r"(b.y));
}

__device__ __forceinline__ void cpa16(uint32_t saddr, const void* g) {
    asm volatile("cp.async.cg.shared.global [%0], [%1], 16;" :: "r"(saddr), "l"(g));
}
__device__ __forceinline__ void cpa_commit() { asm volatile("cp.async.commit_group;"); }
__device__ __forceinline__ void cpa_wait0()  { asm volatile("cp.async.wait_group 0;" ::: "memory"); }

// ============ weight pack kernels ============
__global__ void k_pack_qk(const float* __restrict__ qW, const float* __restrict__ kW)
{
    int idx = blockIdx.x * 256 + threadIdx.x;
    int kk = idx & 3, m = (idx >> 2) & 127, kb = idx >> 9;
    int k0 = kb * 8 + kk;
    const float* wr = (m < 64) ? (qW + (size_t)m * CIN) : (kW + (size_t)(m - 64) * CIN);
    g_Aqk[idx] = make_uint2(f2tf(wr[k0]), f2tf(wr[k0 + 4]));
}

__global__ void k_pack_v(const float* __restrict__ vW)
{
    int idx = blockIdx.x * 256 + threadIdx.x;
    int kk = idx & 3, m = (idx >> 2) & 255, kb = idx >> 10;
    int k0 = kb * 8 + kk;
    const float* wr = vW + (size_t)m * CIN;
    g_Av[idx] = make_uint2(f2tf(wr[k0]), f2tf(wr[k0 + 4]));
}

__global__ void k_pack_conv(const float* __restrict__ sW)
{
    int idx = blockIdx.x * 256 + threadIdx.x;
    int r = idx & 1023, s = idx >> 10;
    int kk = r & 3, co = (r >> 2) & 127, kb = r >> 9;
    int tap = s % 3, t2 = s / 3, ch = t2 & 15, dh = t2 >> 4;
    int ci = ch * 16 + kb * 8 + kk;
    float w0 = sW[((size_t)co * CIN + ci) * 9 + dh * 3 + tap];
    float w1 = sW[((size_t)co * CIN + ci + 4) * 9 + dh * 3 + tap];
    g_wp2[idx] = make_uint2(f2tf(w0), f2tf(w1));
}

// ============ K1: q,k projections + BN + L2 norm (pipelined tf32 mma) ============
// dyn smem: Asm 2x2048 uint2, Bsm 2x2112 uint2, Sq 4x128 f32, Nn 2x128 f32 = 69632 B
__global__ void __launch_bounds__(256, 2)
k_qk_mma(const float* __restrict__ x,
         const float* __restrict__ qs, const float* __restrict__ qb,
         const float* __restrict__ kscale, const float* __restrict__ kshift)
{
    extern __shared__ uint2 dynsm[];
    uint2* Asm = dynsm;              // 2 stages x 2048
    uint2* Bsm = dynsm + 4096;       // 2 stages x 2112
    float* Sq  = (float*)(dynsm + 8320);   // [4][128]
    float* Nn  = Sq + 512;                 // [2][128]

    const int b = blockIdx.y, n0 = blockIdx.x * 128;
    const int tid = threadIdx.x, lane = tid & 31, w = tid >> 5;
    const int g = lane >> 2, kk = lane & 3;
    const int mg = w >> 1, ng = w & 1;
    const int m0w = mg * 32, n0w = ng * 64;
    const int ncol = tid & 127, khi = tid >> 7;

    const uint32_t aBase = (uint32_t)__cvta_generic_to_shared(dynsm);
    const float* xb = x + (size_t)b * CIN * HW + n0;

    float acc[2][8][4];
#pragma unroll
    for (int mt = 0; mt < 2; mt++)
#pragma unroll
        for (int nt = 0; nt < 8; nt++)
#pragma unroll
            for (int i = 0; i < 4; i++) acc[mt][nt][i] = 0.f;

    float bl[8], bh[8];

    // prologue: stage 0
#pragma unroll
    for (int i = 0; i < 4; i++)
        cpa16(aBase + (i * 256 + tid) * 16, g_Aqk + (i * 256 + tid) * 2);
    cpa_commit();
#pragma unroll
    for (int i = 0; i < 8; i++) {
        int kkb = i * 2 + khi;
        int k0 = (kkb >> 2) * 8 + (kkb & 3);
        const float* p = xb + (size_t)k0 * HW + ncol;
        bl[i] = p[0]; bh[i] = p[4 * HW];
    }
#pragma unroll
    for (int i = 0; i < 8; i++) {
        int kkb = i * 2 + khi;
        Bsm[kkb * 132 + ncol] = make_uint2(f2tf(bl[i]), f2tf(bh[i]));
    }
    cpa_wait0();
    __syncthreads();

    for (int it = 0; it < 8; it++) {
        int cur = it & 1, nxt = cur ^ 1;
        if (it < 7) {
#pragma unroll
            for (int i = 0; i < 4; i++)
                cpa16(aBase + nxt * 16384 + (i * 256 + tid) * 16,
                      g_Aqk + (it + 1) * 2048 + (i * 256 + tid) * 2);
            cpa_commit();
            int k0base = (it + 1) * 32;
#pragma unroll
            for (int i = 0; i < 8; i++) {
                int kkb = i * 2 + khi;
                int k0 = k0base + (kkb >> 2) * 8 + (kkb & 3);
                const float* p = xb + (size_t)k0 * HW + ncol;
                bl[i] = p[0]; bh[i] = p[4 * HW];
            }
        }
        const uint2* Ac = Asm + cur * 2048;
        const uint2* Bc = Bsm + cur * 2112;
#pragma unroll
        for (int kb = 0; kb < 4; kb++) {
            uint2 a01[2], a13[2];
#pragma unroll
            for (int mt = 0; mt < 2; mt++) {
                a01[mt] = Ac[(kb * 128 + m0w + mt * 16 + g) * 4 + kk];
                a13[mt] = Ac[(kb * 128 + m0w + mt * 16 + 8 + g) * 4 + kk];
            }
#pragma unroll
            for (int nt = 0; nt < 8; nt++) {
                uint2 bb = Bc[(kb * 4 + kk) * 132 + n0w + nt * 8 + g];
                mma8(acc[0][nt], a01[0], a13[0], bb);
                mma8(acc[1][nt], a01[1], a13[1], bb);
            }
        }
        if (it < 7) {
#pragma unroll
            for (int i = 0; i < 8; i++) {
                int kkb = i * 2 + khi;
                Bsm[nxt * 2112 + kkb * 132 + ncol] = make_uint2(f2tf(bl[i]), f2tf(bh[i]));
            }
        }
        cpa_wait0();
        __syncthreads();
    }

    // BN + column sums of squares
    float sq[8][2];
#pragma unroll
    for (int nt = 0; nt < 8; nt++) { sq[nt][0] = 0.f; sq[nt][1] = 0.f; }
#pragma unroll
    for (int mt = 0; mt < 2; mt++) {
        int r0 = m0w + mt * 16 + g, r1 = r0 + 8;
        bool isq = (r0 < 64);
        float sc0 = isq ? qs[r0] : kscale[r0 - 64];
        float sh0 = isq ? qb[r0] : kshift[r0 - 64];
        float sc1 = isq ? qs[r1] : kscale[r1 - 64];
        float sh1 = isq ? qb[r1] : kshift[r1 - 64];
#pragma unroll
        for (int nt = 0; nt < 8; nt++) {
            float v0 = fmaf(acc[mt][nt][0], sc0, sh0);
            float v1 = fmaf(acc[mt][nt][1], sc0, sh0);
            float v2 = fmaf(acc[mt][nt][2], sc1, sh1);
            float v3 = fmaf(acc[mt][nt][3], sc1, sh1);
            acc[mt][nt][0] = v0; acc[mt][nt][1] = v1;
            acc[mt][nt][2] = v2; acc[mt][nt][3] = v3;
            sq[nt][0] += v0 * v0 + v2 * v2;
            sq[nt][1] += v1 * v1 + v3 * v3;
        }
    }
#pragma unroll
    for (int nt = 0; nt < 8; nt++) {
#pragma unroll
        for (int o = 4; o < 32; o <<= 1) {
            sq[nt][0] += __shfl_xor_sync(0xffffffffu, sq[nt][0], o);
            sq[nt][1] += __shfl_xor_sync(0xffffffffu, sq[nt][1], o);
        }
    }
    if (lane < 4) {
#pragma unroll
        for (int nt = 0; nt < 8; nt++) {
            int c = n0w + nt * 8 + lane * 2;
            Sq[mg * 128 + c] = sq[nt][0];
            Sq[mg * 128 + c + 1] = sq[nt][1];
        }
    }
    __syncthreads();
    {
        int col = tid & 127, half = tid >> 7;
        float s = Sq[half * 256 + col] + Sq[half * 256 + 128 + col];
        Nn[half * 128 + col] = 1.f / fmaxf(sqrtf(s), 1e-12f);
    }
    __syncthreads();

    const int halfW = (mg >= 2) ? 1 : 0;
    float* outb = halfW ? (g_kn + (size_t)b * CQK * HW) : (g_qn + (size_t)b * CQK * HW);
#pragma unroll
    for (int mt = 0; mt < 2; mt++) {
        int r = m0w + mt * 16 + g - halfW * 64;
#pragma unroll
        for (int nt = 0; nt < 8; nt++) {
            int c = n0w + nt * 8 + (lane & 3) * 2;
            float i0 = Nn[halfW * 128 + c], i1 = Nn[halfW * 128 + c + 1];
            float2 o0 = make_float2(acc[mt][nt][0] * i0, acc[mt][nt][1] * i1);
            float2 o1 = make_float2(acc[mt][nt][2] * i0, acc[mt][nt][3] * i1);
            *(float2*)&outb[(size_t)r * HW + n0 + c] = o0;
            *(float2*)&outb[(size_t)(r + 8) * HW + n0 + c] = o1;
        }
    }
}

// ============ K2: v projection + BN + ReLU (pipelined tf32 mma) ============
// dyn smem: Asm 2x2048 + Bsm 2x2112 uint2 = 66560 B
__global__ void __launch_bounds__(256, 2)
k_v_mma(const float* __restrict__ x,
        const float* __restrict__ vs, const float* __restrict__ vb)
{
    extern __shared__ uint2 dynsm[];
    uint2* Asm = dynsm;
    uint2* Bsm = dynsm + 4096;

    const int b = blockIdx.z, co0 = blockIdx.y * 128, n0 = blockIdx.x * 128;
    const int tid = threadIdx.x, lane = tid & 31, w = tid >> 5;
    const int g = lane >> 2, kk = lane & 3;
    const int mg = w >> 1, ng = w & 1;
    const int m0w = mg * 32, n0w = ng * 64;
    const int ncol = tid & 127, khi = tid >> 7;

    const uint32_t aBase = (uint32_t)__cvta_generic_to_shared(dynsm);
    const float* xb = x + (size_t)b * CIN * HW + n0;

    float acc[2][8][4];
#pragma unroll
    for (int mt = 0; mt < 2; mt++)
#pragma unroll
        for (int nt = 0; nt < 8; nt++)
#pragma unroll
            for (int i = 0; i < 4; i++) acc[mt][nt][i] = 0.f;

    float bl[8], bh[8];

#pragma unroll
    for (int i = 0; i < 4; i++) {
        int c = i * 256 + tid;
        cpa16(aBase + c * 16, g_Av + (size_t)(c >> 8) * 1024 + co0 * 4 + (c & 255) * 2);
    }
    cpa_commit();
#pragma unroll
    for (int i = 0; i < 8; i++) {
        int kkb = i * 2 + khi;
        int k0 = (kkb >> 2) * 8 + (kkb & 3);
        const float* p = xb + (size_t)k0 * HW + ncol;
        bl[i] = p[0]; bh[i] = p[4 * HW];
    }
#pragma unroll
    for (int i = 0; i < 8; i++) {
        int kkb = i * 2 + khi;
        Bsm[kkb * 132 + ncol] = make_uint2(f2tf(bl[i]), f2tf(bh[i]));
    }
    cpa_wait0();
    __syncthreads();

    for (int it = 0; it < 8; it++) {
        int cur = it & 1, nxt = cur ^ 1;
        if (it < 7) {
#pragma unroll
            for (int i = 0; i < 4; i++) {
                int c = i * 256 + tid;
                cpa16(aBase + nxt * 16384 + c * 16,
                      g_Av + (size_t)((it + 1) * 4 + (c >> 8)) * 1024 + co0 * 4 + (c & 255) * 2);
            }
            cpa_commit();
            int k0base = (it + 1) * 32;
#pragma unroll
            for (int i = 0; i < 8; i++) {
                int kkb = i * 2 + khi;
                int k0 = k0base + (kkb >> 2) * 8 + (kkb & 3);
                const float* p = xb + (size_t)k0 * HW + ncol;
                bl[i] = p[0]; bh[i] = p[4 * HW];
            }
        }
        const uint2* Ac = Asm + cur * 2048;
        const uint2* Bc = Bsm + cur * 2112;
#pragma unroll
        for (int kb = 0; kb < 4; kb++) {
            uint2 a01[2], a13[2];
#pragma unroll
            for (int mt = 0; mt < 2; mt++) {
                a01[mt] = Ac[(kb * 128 + m0w + mt * 16 + g) * 4 + kk];
                a13[mt] = Ac[(kb * 128 + m0w + mt * 16 + 8 + g) * 4 + kk];
            }
#pragma unroll
            for (int nt = 0; nt < 8; nt++) {
                uint2 bb = Bc[(kb * 4 + kk) * 132 + n0w + nt * 8 + g];
                mma8(acc[0][nt], a01[0], a13[0], bb);
                mma8(acc[1][nt], a01[1], a13[1], bb);
            }
        }
        if (it < 7) {
#pragma unroll
            for (int i = 0; i < 8; i++) {
                int kkb = i * 2 + khi;
                Bsm[nxt * 2112 + kkb * 132 + ncol] = make_uint2(f2tf(bl[i]), f2tf(bh[i]));
            }
        }
        cpa_wait0();
        __syncthreads();
    }

#pragma unroll
    for (int mt = 0; mt < 2; mt++) {
        int co = co0 + m0w + mt * 16 + g;
        float sc0 = vs[co], sh0 = vb[co];
        float sc1 = vs[co + 8], sh1 = vb[co + 8];
        float* o0p = g_v + ((size_t)b * CIN + co) * HW + n0;
        float* o1p = g_v + ((size_t)b * CIN + co + 8) * HW + n0;
#pragma unroll
        for (int nt = 0; nt < 8; nt++) {
            int c = n0w + nt * 8 + (lane & 3) * 2;
            float2 o0 = make_float2(fmaxf(fmaf(acc[mt][nt][0], sc0, sh0), 0.f),
                                    fmaxf(fmaf(acc[mt][nt][1], sc0, sh0), 0.f));
            float2 o1 = make_float2(fmaxf(fmaf(acc[mt][nt][2], sc1, sh1), 0.f),
                                    fmaxf(fmaf(acc[mt][nt][3], sc1, sh1), 0.f));
            *(float2*)&o0p[c] = o0;
            *(float2*)&o1p[c] = o1;
        }
    }
}

// ============ K3: partial sim = kn @ v^T (tf32 mma, vectorized loads) ============
__global__ void __launch_bounds__(256, 2) k_sim_mma()
{
    __shared__ uint2 Asm[1024];
    __shared__ uint2 Bsm[256 * 18];

    const int b = blockIdx.y, ch = blockIdx.x;
    const int p0 = ch * PIX_PER_CHUNK;
    const int tid = threadIdx.x, lane = tid & 31, w = tid >> 5;
    const int g = lane >> 2, kk = lane & 3;
    const int mg = w >> 2, ng = w & 3;
    const int m0w = mg * 32, n0w = ng * 64;

    float acc[2][8][4];
#pragma unroll
    for (int mt = 0; mt < 2; mt++)
#pragma unroll
        for (int nt = 0; nt < 8; nt++)
#pragma unroll
            for (int i = 0; i < 4; i++) acc[mt][nt][i] = 0.f;

    const float* kbp = g_kn + (size_t)b * CQK * HW + p0;
    const float* vbp = g_v + (size_t)b * CIN * HW + p0;
    const int arow = tid >> 2, aqt = tid & 3;

    for (int it = 0; it < 16; it++) {
        int pk = it * 32;
        // A: kn rows, vectorized (each thread: 1 row-quarter = 8 k's)
        {
            const float* kr = kbp + (size_t)arow * HW + pk + aqt * 8;
            float4 a0 = *(const float4*)kr;
            float4 a1 = *(const float4*)(kr + 4);
            uint2* dst = Asm + (aqt * 64 + arow) * 4;
            dst[0] = make_uint2(f2tf(a0.x), f2tf(a1.x));
            dst[1] = make_uint2(f2tf(a0.y), f2tf(a1.y));
            dst[2] = make_uint2(f2tf(a0.z), f2tf(a1.z));
            dst[3] = make_uint2(f2tf(a0.w), f2tf(a1.w));
        }
        // B: v rows, vectorized (each thread: 1 full row of 32 k's)
        {
            const float* vr = vbp + (size_t)tid * HW + pk;
            float4 q0 = *(const float4*)(vr);
            float4 q1 = *(const float4*)(vr + 4);
            float4 q2 = *(const float4*)(vr + 8);
            float4 q3 = *(const float4*)(vr + 12);
            float4 q4 = *(const float4*)(vr + 16);
            float4 q5 = *(const float4*)(vr + 20);
            float4 q6 = *(const float4*)(vr + 24);
            float4 q7 = *(const float4*)(vr + 28);
            uint2* dst = Bsm + tid * 18;
            dst[0]  = make_uint2(f2tf(q0.x), f2tf(q1.x));
            dst[1]  = make_uint2(f2tf(q0.y), f2tf(q1.y));
            dst[2]  = make_uint2(f2tf(q0.z), f2tf(q1.z));
            dst[3]  = make_uint2(f2tf(q0.w), f2tf(q1.w));
            dst[4]  = make_uint2(f2tf(q2.x), f2tf(q3.x));
            dst[5]  = make_uint2(f2tf(q2.y), f2tf(q3.y));
            dst[6]  = make_uint2(f2tf(q2.z), f2tf(q3.z));
            dst[7]  = make_uint2(f2tf(q2.w), f2tf(q3.w));
            dst[8]  = make_uint2(f2tf(q4.x), f2tf(q5.x));
            dst[9]  = make_uint2(f2tf(q4.y), f2tf(q5.y));
            dst[10] = make_uint2(f2tf(q4.z), f2tf(q5.z));
            dst[11] = make_uint2(f2tf(q4.w), f2tf(q5.w));
            dst[12] = make_uint2(f2tf(q6.x), f2tf(q7.x));
            dst[13] = make_uint2(f2tf(q6.y), f2tf(q7.y));
            dst[14] = make_uint2(f2tf(q6.z), f2tf(q7.z));
            dst[15] = make_uint2(f2tf(q6.w), f2tf(q7.w));
        }
        __syncthreads();
#pragma unroll
        for (int kb = 0; kb < 4; kb++) {
            uint2 a01[2], a13[2];
#pragma unroll
            for (int mt = 0; mt < 2; mt++) {
                a01[mt] = Asm[(kb * 64 + m0w + mt * 16 + g) * 4 + kk];
                a13[mt] = Asm[(kb * 64 + m0w + mt * 16 + 8 + g) * 4 + kk];
            }
#pragma unroll
            for (int nt = 0; nt < 8; nt++) {
                uint2 bb = Bsm[(n0w + nt * 8 + g) * 18 + kb * 4 + kk];
                mma8(acc[0][nt], a01[0], a13[0], bb);
                mma8(acc[1][nt], a01[1], a13[1], bb);
            }
        }
        __syncthreads();
    }

    float* outp = g_simp + (size_t)(b * NCH + ch) * CQK * CIN;
#pragma unroll
    for (int mt = 0; mt < 2; mt++) {
        int r = m0w + mt * 16 + g;
#pragma unroll
        for (int nt = 0; nt < 8; nt++) {
            int c = n0w + nt * 8 + (lane & 3) * 2;
            *(float2*)&outp[(size_t)r * CIN + c] = make_float2(acc[mt][nt][0], acc[mt][nt][1]);
            *(float2*)&outp[(size_t)(r + 8) * CIN + c] = make_float2(acc[mt][nt][2], acc[mt][nt][3]);
        }
    }
}

// K3b: reduce partials
__global__ void k_simreduce()
{
    int o = blockIdx.x * 256 + threadIdx.x;
    int b = o / (CQK * CIN);
    int cv = o - b * (CQK * CIN);
    float s = 0.f;
#pragma unroll 8
    for (int ch = 0; ch < NCH; ch++)
        s += g_simp[((size_t)(b * NCH + ch)) * CQK * CIN + cv];
    g_sim[o] = s;
}

// K4a: M2 = oW @ sim^T
__global__ void k_m2(const float* __restrict__ oW)
{
    __shared__ float ssm[CIN];
    const int b = blockIdx.x >> 6;
    const int c = blockIdx.x & 63;
    const int o = threadIdx.x;
    ssm[o] = g_sim[((size_t)b * CQK + c) * CIN + o];
    __syncthreads();
    float s = 0.f;
#pragma unroll 8
    for (int v = 0; v < CIN; v++) s = fmaf(oW[(size_t)o * CIN + v], ssm[v], s);
    g_M2[((size_t)b * CIN + o) * CQK + c] = s;
}

// K4: fuse = relu(BN(M2 @ qn)) + x + bilinear_up
__global__ void k_ctx(const float* __restrict__ x, const float* __restrict__ up,
                      const float* __restrict__ os, const float* __restrict__ ob)
{
    __shared__ float Wt[128][8];
    __shared__ float Xt[8][128];
    __shared__ float upH[128][64];

    const int b = blockIdx.z;
    const int co0 = blockIdx.y * 128;
    const int h = blockIdx.x;
    const int n0 = h * Ww;
    const int tid = threadIdx.x;
    const int ty = tid >> 4, tx = tid & 15;

    {
        float shf = 0.5f * h - 0.25f;
        int h0 = (int)floorf(shf);
        float wh1 = shf - (float)h0;
        int h0c = h0 < 0 ? 0 : h0;
        int h1c = (h0 + 1) > 63 ? 63 : (h0 + 1);
        const float* ub = up + ((size_t)(b * CIN + co0)) * 64 * 64;
#pragma unroll
        for (int i = 0; i < 32; i++) {
            int idx = i * 256 + tid;
            int r = idx >> 6, sw = idx & 63;
            upH[r][sw] = (1.f - wh1) * ub[(r * 64 + h0c) * 64 + sw]
                       + wh1 * ub[(r * 64 + h1c) * 64 + sw];
        }
    }

    float acc[8][8];
#pragma unroll
    for (int r = 0; r < 8; r++)
#pragma unroll
        for (int c = 0; c < 8; c++) acc[r][c] = 0.f;

    const float* qb = g_qn + (size_t)b * CQK * HW;
    const float* Mb = g_M2 + (size_t)b * CIN * CQK;

    for (int kk = 0; kk < CQK; kk += 8) {
#pragma unroll
        for (int i = 0; i < 4; i++) {
            int idx = i * 256 + tid;
            int m = idx >> 3, kl = idx & 7;
            Wt[m][kl] = Mb[(size_t)(co0 + m) * CQK + kk + kl];
        }
#pragma unroll
        for (int i = 0; i < 4; i++) {
            int idx = i * 256 + tid;
            int r = idx >> 7, c = idx & 127;
            Xt[r][c] = qb[(size_t)(kk + r) * HW + n0 + c];
        }
        __syncthreads();
#pragma unroll
        for (int k = 0; k < 8; k++) {
            float wr[8], xr[8];
#pragma unroll
            for (int r = 0; r < 8; r++) wr[r] = Wt[ty * 8 + r][k];
#pragma unroll
            for (int c = 0; c < 8; c++) xr[c] = Xt[k][tx * 8 + c];
#pragma unroll
            for (int r = 0; r < 8; r++)
#pragma unroll
                for (int c = 0; c < 8; c++) acc[r][c] = fmaf(wr[r], xr[c], acc[r][c]);
        }
        __syncthreads();
    }

    float ww1a[8];
    int w0c[8], w1c[8];
#pragma unroll
    for (int c = 0; c < 8; c++) {
        int w = tx * 8 + c;
        float swf = 0.5f * w - 0.25f;
        int w0 = (int)floorf(swf);
        ww1a[c] = swf - (float)w0;
        w0c[c] = w0 < 0 ? 0 : w0;
        w1c[c] = (w0 + 1) > 63 ? 63 : (w0 + 1);
    }
    const float* xb = x + ((size_t)b * CIN + co0) * HW;
    float* fb = g_fuse + ((size_t)b * CIN + co0) * HW;
#pragma unroll
    for (int r = 0; r < 8; r++) {
        int m = ty * 8 + r;
        int co = co0 + m;
        float sc = os[co], sh = ob[co];
#pragma unroll
        for (int c = 0; c < 8; c++) {
            int w = tx * 8 + c;
            float y = fmaxf(fmaf(acc[r][c], sc, sh), 0.f);
            float uv = (1.f - ww1a[c]) * upH[m][w0c[c]] + ww1a[c] * upH[m][w1c[c]];
            fb[(size_t)m * HW + n0 + w] = y + xb[(size_t)m * HW + n0 + w] + uv;
        }
    }
}

// ============ K5: 3x3 conv, 2 rows x 64 co x 128 w per block (tf32 mma) ============
// static smem: Wsm 1536 uint2 (12KB) + Bsm 4224 uint2 (33.8KB) = 46KB
__global__ void __launch_bounds__(256, 2)
k_conv_mma(const float* __restrict__ ss, const float* __restrict__ sb,
           float* __restrict__ out)
{
    __shared__ uint2 Wsm[1536];        // [tap][kb][m64][kk]
    __shared__ uint2 Bsm[4 * 8 * 132]; // [row4][kkb8][col132], col c <-> wx = c-1

    const int h0 = blockIdx.x * 2;
    const int co0 = blockIdx.y * 64;
    const int b = blockIdx.z;
    const int tid = threadIdx.x, lane = tid & 31, w = tid >> 5;
    const int g = lane >> 2, kk = lane & 3;
    const int mg = w >> 2, ng = w & 3;
    const int m0w = mg * 32, n0w = ng * 64;

    float acc[2][8][4];
#pragma unroll
    for (int mt = 0; mt < 2; mt++)
#pragma unroll
        for (int nt = 0; nt < 8; nt++)
#pragma unroll
            for (int i = 0; i < 4; i++) acc[mt][nt][i] = 0.f;

    const float* fbase = g_fuse + (size_t)b * CIN * HW;

    for (int ch = 0; ch < 16; ch++) {
        // input rows h0-1 .. h0+2, 16 ci (8 kkb pairs), 130 cols
        for (int j = tid; j < 4160; j += 256) {
            int col = j % 130;
            int t = j / 130;
            int kkb = t & 7, row = t >> 3;
            int ci = ch * 16 + (kkb >> 2) * 8 + (kkb & 3);
            int hs = h0 - 1 + row;
            int wx = col - 1;
            float v0 = 0.f, v1 = 0.f;
            if (hs >= 0 && hs < Hh && wx >= 0 && wx < Ww) {
                const float* p = fbase + (size_t)ci * HW + hs * Ww + wx;
                v0 = p[0];
                v1 = p[4 * HW];
            }
            Bsm[(row * 8 + kkb) * 132 + col] = make_uint2(f2tf(v0), f2tf(v1));
        }
        for (int dh = 0; dh < 3; dh++) {
#pragma unroll
            for (int i = 0; i < 6; i++) {
                int j = i * 256 + tid;      // < 1536
                int tap = j / 512;
                int rr = j - tap * 512;
                int kbl = rr >> 8, r = rr & 255;
                Wsm[j] = g_wp2[(size_t)(dh * 48 + ch * 3 + tap) * 1024 + kbl * 512 + co0 * 4 + r];
            }
            __syncthreads();
#pragma unroll
            for (int tap = 0; tap < 3; tap++) {
#pragma unroll
                for (int kb = 0; kb < 2; kb++) {
                    uint2 a01[2], a13[2];
#pragma unroll
                    for (int mt = 0; mt < 2; mt++) {
                        a01[mt] = Wsm[tap * 512 + kb * 256 + (m0w + mt * 16 + g) * 4 + kk];
                        a13[mt] = Wsm[tap * 512 + kb * 256 + (m0w + mt * 16 + 8 + g) * 4 + kk];
                    }
#pragma unroll
                    for (int nt = 0; nt < 8; nt++) {
                        int n = n0w + nt * 8 + g;
                        int r = n >> 7, wx = n & 127;
                        uint2 bb = Bsm[((r + dh) * 8 + kb * 4 + kk) * 132 + wx + tap];
                        mma8(acc[0][nt], a01[0], a13[0], bb);
                        mma8(acc[1][nt], a01[1], a13[1], bb);
                    }
                }
            }
            __syncthreads();
        }
    }

#pragma unroll
    for (int mt = 0; mt < 2; mt++) {
        int co = co0 + m0w + mt * 16 + g;
        float sc0 = ss[co], sh0 = sb[co];
        float sc1 = ss[co + 8], sh1 = sb[co + 8];
#pragma unroll
        for (int nt = 0; nt < 8; nt++) {
            int n = n0w + nt * 8 + (lane & 3) * 2;
            int r = n >> 7, wx = n & 127;
            float* o0p = out + (((size_t)b * CS + co) * Hh + h0 + r) * Ww + wx;
            float* o1p = out + (((size_t)b * CS + co + 8) * Hh + h0 + r) * Ww + wx;
            float2 o0 = make_float2(fmaxf(fmaf(acc[mt][nt][0], sc0, sh0), 0.f),
                                    fmaxf(fmaf(acc[mt][nt][1], sc0, sh0), 0.f));
            float2 o1 = make_float2(fmaxf(fmaf(acc[mt][nt][2], sc1, sh1), 0.f),
                                    fmaxf(fmaf(acc[mt][nt][3], sc1, sh1), 0.f));
            *(float2*)o0p = o0;
            *(float2*)o1p = o1;
        }
    }
}

// ============================================================
extern "C" void kernel_launch(void* const* d_in, const int* in_sizes, int n_in,
                              void* d_out, int out_size)
{
    (void)in_sizes; (void)n_in; (void)out_size;
    const float* x        = (const float*)d_in[0];
    const float* up       = (const float*)d_in[1];
    const float* qW       = (const float*)d_in[2];
    const float* q_scale  = (const float*)d_in[3];
    const float* q_shift  = (const float*)d_in[4];
    const float* kW       = (const float*)d_in[5];
    const float* k_scale  = (const float*)d_in[6];
    const float* k_shift  = (const float*)d_in[7];
    const float* vW       = (const float*)d_in[8];
    const float* v_scale  = (const float*)d_in[9];
    const float* v_shift  = (const float*)d_in[10];
    const float* oW       = (const float*)d_in[11];
    const float* o_scale  = (const float*)d_in[12];
    const float* o_shift  = (const float*)d_in[13];
    const float* sW       = (const float*)d_in[14];
    const float* s_scale  = (const float*)d_in[15];
    const float* s_shift  = (const float*)d_in[16];
    float* out = (float*)d_out;

    cudaFuncSetAttribute(k_qk_mma, cudaFuncAttributeMaxDynamicSharedMemorySize, 69632);
    cudaFuncSetAttribute(k_v_mma, cudaFuncAttributeMaxDynamicSharedMemorySize, 66560);

    k_pack_qk<<<64, 256>>>(qW, kW);
    k_pack_v<<<128, 256>>>(vW);
    k_pack_conv<<<576, 256>>>(sW);
    k_qk_mma<<<dim3(HW / 128, Bn), 256, 69632>>>(x, q_scale, q_shift, k_scale, k_shift);
    k_v_mma<<<dim3(HW / 128, 2, Bn), 256, 66560>>>(x, v_scale, v_shift);
    k_sim_mma<<<dim3(NCH, Bn), 256>>>();
    k_simreduce<<<256, 256>>>();
    k_m2<<<Bn * CQK, 256>>>(oW);
    k_ctx<<<dim3(Hh, 2, Bn), 256>>>(x, up, o_scale, o_shift);
    k_conv_mma<<<dim3(Hh / 2, 2, Bn), 256>>>(s_scale, s_shift, out);
}

// round 4
// speedup vs baseline: 3.1914x; 1.1314x over previous
#include <cuda_runtime.h>
#include <math.h>
#include <stdint.h>

#define Bn   4
#define CIN  256
#define CQK  64
#define CS   128
#define Hh   128
#define Ww   128
#define HW   (Hh*Ww)
#define NCH  32
#define PIX_PER_CHUNK (HW/NCH)     // 512

// ---- scratch ----
__device__ float g_qn  [Bn*CQK*HW];
__device__ float g_kn  [Bn*CQK*HW];
__device__ float g_v   [Bn*CIN*HW];
__device__ float g_simp[Bn*NCH*CQK*CIN];
__device__ float g_sim [Bn*CQK*CIN];
__device__ float g_M2  [Bn*CIN*CQK];

// packed tf32 pair buffers (zero-initialized .bss; borders of g_ft stay zero)
__device__ __align__(16) uint2 g_Aqk[16384];            // qk weights
__device__ __align__(16) uint2 g_Av [32768];            // v weights
__device__ __align__(16) uint2 g_wp2[147456];           // conv weights
__device__ __align__(16) uint2 g_xt [Bn*8*16*HW];       // x packed: [(b*8+it)*16+kkb][n]
__device__ __align__(16) uint2 g_ft [Bn*128*130*132];   // fuse packed+padded: [b*128+ch*8+kkb][h+1][w+1]

__device__ __forceinline__ uint32_t f2tf(float f) {
    uint32_t u; asm("cvt.rna.tf32.f32 %0, %1;" : "=r"(u) : "f"(f)); return u;
}

__device__ __forceinline__ void mma8(float* c, uint2 a01, uint2 a13, uint2 b) {
    asm volatile(
        "mma.sync.aligned.m16n8k8.row.col.f32.tf32.tf32.f32 "
        "{%0,%1,%2,%3}, {%4,%5,%6,%7}, {%8,%9}, {%0,%1,%2,%3};"
        : "+f"(c[0]), "+f"(c[1]), "+f"(c[2]), "+f"(c[3])
        : "r"(a01.x), "r"(a13.x), "r"(a01.y), "r"(a13.y), "r"(b.x), "r"(b.y));
}

__device__ __forceinline__ void cpa16(uint32_t saddr, const void* g) {
    asm volatile("cp.async.cg.shared.global [%0], [%1], 16;" :: "r"(saddr), "l"(g));
}
__device__ __forceinline__ void cpa_commit() { asm volatile("cp.async.commit_group;"); }
__device__ __forceinline__ void cpa_wait0()  { asm volatile("cp.async.wait_group 0;" ::: "memory"); }

// ============ pack kernels ============
__global__ void k_pack_qk(const float* __restrict__ qW, const float* __restrict__ kW)
{
    int idx = blockIdx.x * 256 + threadIdx.x;
    int kk = idx & 3, m = (idx >> 2) & 127, kb = idx >> 9;
    int k0 = kb * 8 + kk;
    const float* wr = (m < 64) ? (qW + (size_t)m * CIN) : (kW + (size_t)(m - 64) * CIN);
    g_Aqk[idx] = make_uint2(f2tf(wr[k0]), f2tf(wr[k0 + 4]));
}

__global__ void k_pack_v(const float* __restrict__ vW)
{
    int idx = blockIdx.x * 256 + threadIdx.x;
    int kk = idx & 3, m = (idx >> 2) & 255, kb = idx >> 10;
    int k0 = kb * 8 + kk;
    const float* wr = vW + (size_t)m * CIN;
    g_Av[idx] = make_uint2(f2tf(wr[k0]), f2tf(wr[k0 + 4]));
}

__global__ void k_pack_conv(const float* __restrict__ sW)
{
    int idx = blockIdx.x * 256 + threadIdx.x;
    int r = idx & 1023, s = idx >> 10;
    int kk = r & 3, co = (r >> 2) & 127, kb = r >> 9;
    int tap = s % 3, t2 = s / 3, ch = t2 & 15, dh = t2 >> 4;
    int ci = ch * 16 + kb * 8 + kk;
    float w0 = sW[((size_t)co * CIN + ci) * 9 + dh * 3 + tap];
    float w1 = sW[((size_t)co * CIN + ci + 4) * 9 + dh * 3 + tap];
    g_wp2[idx] = make_uint2(f2tf(w0), f2tf(w1));
}

// x -> tf32 pair layout [(b*8+it)*16+kkb][n]
__global__ void k_packx(const float* __restrict__ x)
{
    int idx = blockIdx.x * 256 + threadIdx.x;   // < 8388608
    int n = idx & 16383;
    int kkb = (idx >> 14) & 15;
    int it = (idx >> 18) & 7;
    int b = idx >> 21;
    int k0 = it * 32 + ((kkb >> 2) << 3) + (kkb & 3);
    const float* xb = x + ((size_t)b * CIN + k0) * HW + n;
    g_xt[idx] = make_uint2(f2tf(xb[0]), f2tf(xb[4 * HW]));
}

// ============ K1: q,k projections + BN + L2 norm (all-cp.async pipelined) ============
// dyn smem: Asm 2x2048 uint2, Bsm 2x2112 uint2, Sq 4x128 f32, Nn 2x128 f32 = 69632 B
__global__ void __launch_bounds__(256, 2)
k_qk_mma(const float* __restrict__ qs, const float* __restrict__ qb,
         const float* __restrict__ kscale, const float* __restrict__ kshift)
{
    extern __shared__ uint2 dynsm[];
    uint2* Asm = dynsm;              // 2 x 2048
    uint2* Bsm = dynsm + 4096;       // 2 x 2112
    float* Sq  = (float*)(dynsm + 8320);
    float* Nn  = Sq + 512;

    const int b = blockIdx.y, n0 = blockIdx.x * 128;
    const int tid = threadIdx.x, lane = tid & 31, w = tid >> 5;
    const int g = lane >> 2, kk = lane & 3;
    const int mg = w >> 1, ng = w & 1;
    const int m0w = mg * 32, n0w = ng * 64;

    const uint32_t aBase = (uint32_t)__cvta_generic_to_shared(dynsm);
    const uint2* xtb = g_xt + (size_t)b * 8 * 16 * HW + n0;

    float acc[2][8][4];
#pragma unroll
    for (int mt = 0; mt < 2; mt++)
#pragma unroll
        for (int nt = 0; nt < 8; nt++)
#pragma unroll
            for (int i = 0; i < 4; i++) acc[mt][nt][i] = 0.f;

    // prologue: stage 0
#pragma unroll
    for (int i = 0; i < 4; i++) {
        int j = i * 256 + tid;
        cpa16(aBase + j * 16, g_Aqk + j * 2);
    }
#pragma unroll
    for (int i = 0; i < 4; i++) {
        int j = i * 256 + tid;                 // < 1024
        int kkb = j >> 6, npair = (j & 63) * 2;
        cpa16(aBase + 4096 * 8 + (kkb * 132 + npair) * 8,
              xtb + (size_t)kkb * HW + npair);
    }
    cpa_commit();
    cpa_wait0();
    __syncthreads();

    for (int it = 0; it < 8; it++) {
        int cur = it & 1, nxt = cur ^ 1;
        if (it < 7) {
#pragma unroll
            for (int i = 0; i < 4; i++) {
                int j = i * 256 + tid;
                cpa16(aBase + nxt * 16384 + j * 16, g_Aqk + (it + 1) * 2048 + j * 2);
            }
#pragma unroll
            for (int i = 0; i < 4; i++) {
                int j = i * 256 + tid;
                int kkb = j >> 6, npair = (j & 63) * 2;
                cpa16(aBase + 4096 * 8 + nxt * 16896 + (kkb * 132 + npair) * 8,
                      xtb + (size_t)((it + 1) * 16 + kkb) * HW + npair);
            }
            cpa_commit();
        }
        const uint2* Ac = Asm + cur * 2048;
        const uint2* Bc = Bsm + cur * 2112;
#pragma unroll
        for (int kb = 0; kb < 4; kb++) {
            uint2 a01[2], a13[2];
#pragma unroll
            for (int mt = 0; mt < 2; mt++) {
                a01[mt] = Ac[(kb * 128 + m0w + mt * 16 + g) * 4 + kk];
                a13[mt] = Ac[(kb * 128 + m0w + mt * 16 + 8 + g) * 4 + kk];
            }
#pragma unroll
            for (int nt = 0; nt < 8; nt++) {
                uint2 bb = Bc[(kb * 4 + kk) * 132 + n0w + nt * 8 + g];
                mma8(acc[0][nt], a01[0], a13[0], bb);
                mma8(acc[1][nt], a01[1], a13[1], bb);
            }
        }
        cpa_wait0();
        __syncthreads();
    }

    // BN + column sums of squares
    float sq[8][2];
#pragma unroll
    for (int nt = 0; nt < 8; nt++) { sq[nt][0] = 0.f; sq[nt][1] = 0.f; }
#pragma unroll
    for (int mt = 0; mt < 2; mt++) {
        int r0 = m0w + mt * 16 + g, r1 = r0 + 8;
        bool isq = (r0 < 64);
        float sc0 = isq ? qs[r0] : kscale[r0 - 64];
        float sh0 = isq ? qb[r0] : kshift[r0 - 64];
        float sc1 = isq ? qs[r1] : kscale[r1 - 64];
        float sh1 = isq ? qb[r1] : kshift[r1 - 64];
#pragma unroll
        for (int nt = 0; nt < 8; nt++) {
            float v0 = fmaf(acc[mt][nt][0], sc0, sh0);
            float v1 = fmaf(acc[mt][nt][1], sc0, sh0);
            float v2 = fmaf(acc[mt][nt][2], sc1, sh1);
            float v3 = fmaf(acc[mt][nt][3], sc1, sh1);
            acc[mt][nt][0] = v0; acc[mt][nt][1] = v1;
            acc[mt][nt][2] = v2; acc[mt][nt][3] = v3;
            sq[nt][0] += v0 * v0 + v2 * v2;
            sq[nt][1] += v1 * v1 + v3 * v3;
        }
    }
#pragma unroll
    for (int nt = 0; nt < 8; nt++) {
#pragma unroll
        for (int o = 4; o < 32; o <<= 1) {
            sq[nt][0] += __shfl_xor_sync(0xffffffffu, sq[nt][0], o);
            sq[nt][1] += __shfl_xor_sync(0xffffffffu, sq[nt][1], o);
        }
    }
    if (lane < 4) {
#pragma unroll
        for (int nt = 0; nt < 8; nt++) {
            int c = n0w + nt * 8 + lane * 2;
            Sq[mg * 128 + c] = sq[nt][0];
            Sq[mg * 128 + c + 1] = sq[nt][1];
        }
    }
    __syncthreads();
    {
        int col = tid & 127, half = tid >> 7;
        float s = Sq[half * 256 + col] + Sq[half * 256 + 128 + col];
        Nn[half * 128 + col] = 1.f / fmaxf(sqrtf(s), 1e-12f);
    }
    __syncthreads();

    const int halfW = (mg >= 2) ? 1 : 0;
    float* outb = halfW ? (g_kn + (size_t)b * CQK * HW) : (g_qn + (size_t)b * CQK * HW);
#pragma unroll
    for (int mt = 0; mt < 2; mt++) {
        int r = m0w + mt * 16 + g - halfW * 64;
#pragma unroll
        for (int nt = 0; nt < 8; nt++) {
            int c = n0w + nt * 8 + (lane & 3) * 2;
            float i0 = Nn[halfW * 128 + c], i1 = Nn[halfW * 128 + c + 1];
            float2 o0 = make_float2(acc[mt][nt][0] * i0, acc[mt][nt][1] * i1);
            float2 o1 = make_float2(acc[mt][nt][2] * i0, acc[mt][nt][3] * i1);
            *(float2*)&outb[(size_t)r * HW + n0 + c] = o0;
            *(float2*)&outb[(size_t)(r + 8) * HW + n0 + c] = o1;
        }
    }
}

// ============ K2: v projection + BN + ReLU (all-cp.async pipelined) ============
// dyn smem: Asm 2x2048 + Bsm 2x2112 uint2 = 66560 B
__global__ void __launch_bounds__(256, 2)
k_v_mma(const float* __restrict__ vs, const float* __restrict__ vb)
{
    extern __shared__ uint2 dynsm[];
    uint2* Asm = dynsm;
    uint2* Bsm = dynsm + 4096;

    const int b = blockIdx.z, co0 = blockIdx.y * 128, n0 = blockIdx.x * 128;
    const int tid = threadIdx.x, lane = tid & 31, w = tid >> 5;
    const int g = lane >> 2, kk = lane & 3;
    const int mg = w >> 1, ng = w & 1;
    const int m0w = mg * 32, n0w = ng * 64;

    const uint32_t aBase = (uint32_t)__cvta_generic_to_shared(dynsm);
    const uint2* xtb = g_xt + (size_t)b * 8 * 16 * HW + n0;

    float acc[2][8][4];
#pragma unroll
    for (int mt = 0; mt < 2; mt++)
#pragma unroll
        for (int nt = 0; nt < 8; nt++)
#pragma unroll
            for (int i = 0; i < 4; i++) acc[mt][nt][i] = 0.f;

#pragma unroll
    for (int i = 0; i < 4; i++) {
        int j = i * 256 + tid;
        int u = j * 2, kbl = u >> 9, r = u & 511;
        cpa16(aBase + u * 8, g_Av + (size_t)kbl * 1024 + co0 * 4 + r);
    }
#pragma unroll
    for (int i = 0; i < 4; i++) {
        int j = i * 256 + tid;
        int kkb = j >> 6, npair = (j & 63) * 2;
        cpa16(aBase + 4096 * 8 + (kkb * 132 + npair) * 8,
              xtb + (size_t)kkb * HW + npair);
    }
    cpa_commit();
    cpa_wait0();
    __syncthreads();

    for (int it = 0; it < 8; it++) {
        int cur = it & 1, nxt = cur ^ 1;
        if (it < 7) {
#pragma unroll
            for (int i = 0; i < 4; i++) {
                int j = i * 256 + tid;
                int u = j * 2, kbl = u >> 9, r = u & 511;
                cpa16(aBase + nxt * 16384 + u * 8,
                      g_Av + (size_t)((it + 1) * 4 + kbl) * 1024 + co0 * 4 + r);
            }
#pragma unroll
            for (int i = 0; i < 4; i++) {
                int j = i * 256 + tid;
                int kkb = j >> 6, npair = (j & 63) * 2;
                cpa16(aBase + 4096 * 8 + nxt * 16896 + (kkb * 132 + npair) * 8,
                      xtb + (size_t)((it + 1) * 16 + kkb) * HW + npair);
            }
            cpa_commit();
        }
        const uint2* Ac = Asm + cur * 2048;
        const uint2* Bc = Bsm + cur * 2112;
#pragma unroll
        for (int kb = 0; kb < 4; kb++) {
            uint2 a01[2], a13[2];
#pragma unroll
            for (int mt = 0; mt < 2; mt++) {
                a01[mt] = Ac[(kb * 128 + m0w + mt * 16 + g) * 4 + kk];
                a13[mt] = Ac[(kb * 128 + m0w + mt * 16 + 8 + g) * 4 + kk];
            }
#pragma unroll
            for (int nt = 0; nt < 8; nt++) {
                uint2 bb = Bc[(kb * 4 + kk) * 132 + n0w + nt * 8 + g];
                mma8(acc[0][nt], a01[0], a13[0], bb);
                mma8(acc[1][nt], a01[1], a13[1], bb);
            }
        }
        cpa_wait0();
        __syncthreads();
    }

#pragma unroll
    for (int mt = 0; mt < 2; mt++) {
        int co = co0 + m0w + mt * 16 + g;
        float sc0 = vs[co], sh0 = vb[co];
        float sc1 = vs[co + 8], sh1 = vb[co + 8];
        float* o0p = g_v + ((size_t)b * CIN + co) * HW + n0;
        float* o1p = g_v + ((size_t)b * CIN + co + 8) * HW + n0;
#pragma unroll
        for (int nt = 0; nt < 8; nt++) {
            int c = n0w + nt * 8 + (lane & 3) * 2;
            float2 o0 = make_float2(fmaxf(fmaf(acc[mt][nt][0], sc0, sh0), 0.f),
                                    fmaxf(fmaf(acc[mt][nt][1], sc0, sh0), 0.f));
            float2 o1 = make_float2(fmaxf(fmaf(acc[mt][nt][2], sc1, sh1), 0.f),
                                    fmaxf(fmaf(acc[mt][nt][3], sc1, sh1), 0.f));
            *(float2*)&o0p[c] = o0;
            *(float2*)&o1p[c] = o1;
        }
    }
}

// ============ K3: partial sim = kn @ v^T (tf32 mma, vectorized) ============
__global__ void __launch_bounds__(256, 2) k_sim_mma()
{
    __shared__ uint2 Asm[1024];
    __shared__ uint2 Bsm[256 * 18];

    const int b = blockIdx.y, ch = blockIdx.x;
    const int p0 = ch * PIX_PER_CHUNK;
    const int tid = threadIdx.x, lane = tid & 31, w = tid >> 5;
    const int g = lane >> 2, kk = lane & 3;
    const int mg = w >> 2, ng = w & 3;
    const int m0w = mg * 32, n0w = ng * 64;

    float acc[2][8][4];
#pragma unroll
    for (int mt = 0; mt < 2; mt++)
#pragma unroll
        for (int nt = 0; nt < 8; nt++)
#pragma unroll
            for (int i = 0; i < 4; i++) acc[mt][nt][i] = 0.f;

    const float* kbp = g_kn + (size_t)b * CQK * HW + p0;
    const float* vbp = g_v + (size_t)b * CIN * HW + p0;
    const int arow = tid >> 2, aqt = tid & 3;

    for (int it = 0; it < 16; it++) {
        int pk = it * 32;
        {
            const float* kr = kbp + (size_t)arow * HW + pk + aqt * 8;
            float4 a0 = *(const float4*)kr;
            float4 a1 = *(const float4*)(kr + 4);
            uint2* dst = Asm + (aqt * 64 + arow) * 4;
            dst[0] = make_uint2(f2tf(a0.x), f2tf(a1.x));
            dst[1] = make_uint2(f2tf(a0.y), f2tf(a1.y));
            dst[2] = make_uint2(f2tf(a0.z), f2tf(a1.z));
            dst[3] = make_uint2(f2tf(a0.w), f2tf(a1.w));
        }
        {
            const float* vr = vbp + (size_t)tid * HW + pk;
            float4 q0 = *(const float4*)(vr);
            float4 q1 = *(const float4*)(vr + 4);
            float4 q2 = *(const float4*)(vr + 8);
            float4 q3 = *(const float4*)(vr + 12);
            float4 q4 = *(const float4*)(vr + 16);
            float4 q5 = *(const float4*)(vr + 20);
            float4 q6 = *(const float4*)(vr + 24);
            float4 q7 = *(const float4*)(vr + 28);
            uint2* dst = Bsm + tid * 18;
            dst[0]  = make_uint2(f2tf(q0.x), f2tf(q1.x));
            dst[1]  = make_uint2(f2tf(q0.y), f2tf(q1.y));
            dst[2]  = make_uint2(f2tf(q0.z), f2tf(q1.z));
            dst[3]  = make_uint2(f2tf(q0.w), f2tf(q1.w));
            dst[4]  = make_uint2(f2tf(q2.x), f2tf(q3.x));
            dst[5]  = make_uint2(f2tf(q2.y), f2tf(q3.y));
            dst[6]  = make_uint2(f2tf(q2.z), f2tf(q3.z));
            dst[7]  = make_uint2(f2tf(q2.w), f2tf(q3.w));
            dst[8]  = make_uint2(f2tf(q4.x), f2tf(q5.x));
            dst[9]  = make_uint2(f2tf(q4.y), f2tf(q5.y));
            dst[10] = make_uint2(f2tf(q4.z), f2tf(q5.z));
            dst[11] = make_uint2(f2tf(q4.w), f2tf(q5.w));
            dst[12] = make_uint2(f2tf(q6.x), f2tf(q7.x));
            dst[13] = make_uint2(f2tf(q6.y), f2tf(q7.y));
            dst[14] = make_uint2(f2tf(q6.z), f2tf(q7.z));
            dst[15] = make_uint2(f2tf(q6.w), f2tf(q7.w));
        }
        __syncthreads();
#pragma unroll
        for (int kb = 0; kb < 4; kb++) {
            uint2 a01[2], a13[2];
#pragma unroll
            for (int mt = 0; mt < 2; mt++) {
                a01[mt] = Asm[(kb * 64 + m0w + mt * 16 + g) * 4 + kk];
                a13[mt] = Asm[(kb * 64 + m0w + mt * 16 + 8 + g) * 4 + kk];
            }
#pragma unroll
            for (int nt = 0; nt < 8; nt++) {
                uint2 bb = Bsm[(n0w + nt * 8 + g) * 18 + kb * 4 + kk];
                mma8(acc[0][nt], a01[0], a13[0], bb);
                mma8(acc[1][nt], a01[1], a13[1], bb);
            }
        }
        __syncthreads();
    }

    float* outp = g_simp + (size_t)(b * NCH + ch) * CQK * CIN;
#pragma unroll
    for (int mt = 0; mt < 2; mt++) {
        int r = m0w + mt * 16 + g;
#pragma unroll
        for (int nt = 0; nt < 8; nt++) {
            int c = n0w + nt * 8 + (lane & 3) * 2;
            *(float2*)&outp[(size_t)r * CIN + c] = make_float2(acc[mt][nt][0], acc[mt][nt][1]);
            *(float2*)&outp[(size_t)(r + 8) * CIN + c] = make_float2(acc[mt][nt][2], acc[mt][nt][3]);
        }
    }
}

// K3b: reduce partials
__global__ void k_simreduce()
{
    int o = blockIdx.x * 256 + threadIdx.x;
    int b = o / (CQK * CIN);
    int cv = o - b * (CQK * CIN);
    float s = 0.f;
#pragma unroll 8
    for (int ch = 0; ch < NCH; ch++)
        s += g_simp[((size_t)(b * NCH + ch)) * CQK * CIN + cv];
    g_sim[o] = s;
}

// K4a: M2 = oW @ sim^T
__global__ void k_m2(const float* __restrict__ oW)
{
    __shared__ float ssm[CIN];
    const int b = blockIdx.x >> 6;
    const int c = blockIdx.x & 63;
    const int o = threadIdx.x;
    ssm[o] = g_sim[((size_t)b * CQK + c) * CIN + o];
    __syncthreads();
    float s = 0.f;
#pragma unroll 8
    for (int v = 0; v < CIN; v++) s = fmaf(oW[(size_t)o * CIN + v], ssm[v], s);
    g_M2[((size_t)b * CIN + o) * CQK + c] = s;
}

// K4: fuse = relu(BN(M2 @ qn)) + x + bilinear_up -> write packed tf32 pairs g_ft
__global__ void k_ctx(const float* __restrict__ x, const float* __restrict__ up,
                      const float* __restrict__ os, const float* __restrict__ ob)
{
    __shared__ float Wt[128][8];
    __shared__ float Xt[8][128];
    __shared__ float upH[128][64];

    const int b = blockIdx.z;
    const int co0 = blockIdx.y * 128;
    const int h = blockIdx.x;
    const int n0 = h * Ww;
    const int tid = threadIdx.x;
    const int ty = tid >> 4, tx = tid & 15;

    {
        float shf = 0.5f * h - 0.25f;
        int h0 = (int)floorf(shf);
        float wh1 = shf - (float)h0;
        int h0c = h0 < 0 ? 0 : h0;
        int h1c = (h0 + 1) > 63 ? 63 : (h0 + 1);
        const float* ub = up + ((size_t)(b * CIN + co0)) * 64 * 64;
#pragma unroll
        for (int i = 0; i < 32; i++) {
            int idx = i * 256 + tid;
            int r = idx >> 6, sw = idx & 63;
            upH[r][sw] = (1.f - wh1) * ub[(r * 64 + h0c) * 64 + sw]
                       + wh1 * ub[(r * 64 + h1c) * 64 + sw];
        }
    }

    float acc[8][8];
#pragma unroll
    for (int r = 0; r < 8; r++)
#pragma unroll
        for (int c = 0; c < 8; c++) acc[r][c] = 0.f;

    const float* qb = g_qn + (size_t)b * CQK * HW;
    const float* Mb = g_M2 + (size_t)b * CIN * CQK;

    for (int kk = 0; kk < CQK; kk += 8) {
#pragma unroll
        for (int i = 0; i < 4; i++) {
            int idx = i * 256 + tid;
            int m = idx >> 3, kl = idx & 7;
            Wt[m][kl] = Mb[(size_t)(co0 + m) * CQK + kk + kl];
        }
#pragma unroll
        for (int i = 0; i < 4; i++) {
            int idx = i * 256 + tid;
            int r = idx >> 7, c = idx & 127;
            Xt[r][c] = qb[(size_t)(kk + r) * HW + n0 + c];
        }
        __syncthreads();
#pragma unroll
        for (int k = 0; k < 8; k++) {
            float wr[8], xr[8];
#pragma unroll
            for (int r = 0; r < 8; r++) wr[r] = Wt[ty * 8 + r][k];
#pragma unroll
            for (int c = 0; c < 8; c++) xr[c] = Xt[k][tx * 8 + c];
#pragma unroll
            for (int r = 0; r < 8; r++)
#pragma unroll
                for (int c = 0; c < 8; c++) acc[r][c] = fmaf(wr[r], xr[c], acc[r][c]);
        }
        __syncthreads();
    }

    float ww1a[8];
    int w0c[8], w1c[8];
#pragma unroll
    for (int c = 0; c < 8; c++) {
        int w = tx * 8 + c;
        float swf = 0.5f * w - 0.25f;
        int w0 = (int)floorf(swf);
        ww1a[c] = swf - (float)w0;
        w0c[c] = w0 < 0 ? 0 : w0;
        w1c[c] = (w0 + 1) > 63 ? 63 : (w0 + 1);
    }
    const float* xb = x + ((size_t)b * CIN + co0) * HW;
#pragma unroll
    for (int r = 0; r < 8; r++) {
        int m = ty * 8 + r;
        int co = co0 + m;
        float sc = os[co], sh = ob[co];
#pragma unroll
        for (int c = 0; c < 8; c++) {
            int w = tx * 8 + c;
            float y = fmaxf(fmaf(acc[r][c], sc, sh), 0.f);
            float uv = (1.f - ww1a[c]) * upH[m][w0c[c]] + ww1a[c] * upH[m][w1c[c]];
            acc[r][c] = y + xb[(size_t)m * HW + n0 + w] + uv;
        }
    }
    // pack pairs (m, m+4) -> g_ft with +1 row/col padding
#pragma unroll
    for (int r = 0; r < 4; r++) {
        int m = ty * 8 + r;
        int ci = co0 + m;
        int low = ci & 15, ch = ci >> 4;
        int kkb = (low & 3) | ((low >> 3) << 2);
        uint2* dst = g_ft + ((size_t)(b * 128 + ch * 8 + kkb) * 130 + h + 1) * 132 + 1;
#pragma unroll
        for (int c = 0; c < 8; c++) {
            int w = tx * 8 + c;
            dst[w] = make_uint2(f2tf(acc[r][c]), f2tf(acc[r + 4][c]));
        }
    }
}

// ============ K5: 3x3 conv, 2 rows x 64 co x 128 w, 32-stage pipeline ============
// dyn smem: Ism 2x2112 + Wsm 2x2304 uint2 = 70656 B
__global__ void __launch_bounds__(256, 2)
k_conv_mma(const float* __restrict__ ss, const float* __restrict__ sb,
           float* __restrict__ out)
{
    extern __shared__ uint2 csm[];
    uint2* Ism = csm;            // 2 x 2112: [row4][kkbl4][132]
    uint2* Wsm = csm + 4224;     // 2 x 2304: [dh*3+tap][256]

    const int h0 = blockIdx.x * 2;
    const int co0 = blockIdx.y * 64;
    const int b = blockIdx.z;
    const int tid = threadIdx.x, lane = tid & 31, w = tid >> 5;
    const int g = lane >> 2, kk = lane & 3;
    const int mg = w >> 2, ng = w & 3;
    const int m0w = mg * 32, n0w = ng * 64;
    const uint32_t smBase = (uint32_t)__cvta_generic_to_shared(csm);

    float acc[2][8][4];
#pragma unroll
    for (int mt = 0; mt < 2; mt++)
#pragma unroll
        for (int nt = 0; nt < 8; nt++)
#pragma unroll
            for (int i = 0; i < 4; i++) acc[mt][nt][i] = 0.f;

    const uint2* ftb = g_ft + (size_t)b * 128 * 130 * 132;

    // fill stage for iteration it
    auto fill = [&](int it, int stage) {
        int ch = it >> 1, kbh = it & 1;
        for (int j = tid; j < 1056; j += 256) {
            int rowplane = j / 66;             // row*4 + kkbl
            int colpair = (j - rowplane * 66) * 2;
            int row = rowplane >> 2, kkbl = rowplane & 3;
            cpa16(smBase + (stage * 2112 + (row * 4 + kkbl) * 132 + colpair) * 8,
                  ftb + ((size_t)(ch * 8 + kbh * 4 + kkbl) * 130 + h0 + row) * 132 + colpair);
        }
        for (int j = tid; j < 1152; j += 256) {
            int u = j * 2;
            int grp = u >> 8, off = u & 255;   // grp = dh*3+tap
            int dh = grp / 3, tap = grp - dh * 3;
            cpa16(smBase + (4224 + stage * 2304 + grp * 256 + off) * 8,
                  g_wp2 + (size_t)(dh * 48 + ch * 3 + tap) * 1024 + kbh * 512 + co0 * 4 + off);
        }
    };

    fill(0, 0);
    cpa_commit();
    cpa_wait0();
    __syncthreads();

    for (int it = 0; it < 32; it++) {
        int cur = it & 1, nxt = cur ^ 1;
        if (it < 31) { fill(it + 1, nxt); cpa_commit(); }

        const uint2* Ic = Ism + cur * 2112;
        const uint2* Wc = Wsm + cur * 2304;
#pragma unroll
        for (int dh = 0; dh < 3; dh++) {
#pragma unroll
            for (int tap = 0; tap < 3; tap++) {
                const uint2* wb = Wc + (dh * 3 + tap) * 256;
                uint2 a01[2], a13[2];
#pragma unroll
                for (int mt = 0; mt < 2; mt++) {
                    a01[mt] = wb[(m0w + mt * 16 + g) * 4 + kk];
                    a13[mt] = wb[(m0w + mt * 16 + 8 + g) * 4 + kk];
                }
#pragma unroll
                for (int nt = 0; nt < 8; nt++) {
                    int n = n0w + nt * 8 + g;
                    int rrow = n >> 7, wx = n & 127;
                    uint2 bb = Ic[((rrow + dh) * 4 + kk) * 132 + wx + tap];
                    mma8(acc[0][nt], a01[0], a13[0], bb);
                    mma8(acc[1][nt], a01[1], a13[1], bb);
                }
            }
        }
        cpa_wait0();
        __syncthreads();
    }

#pragma unroll
    for (int mt = 0; mt < 2; mt++) {
        int co = co0 + m0w + mt * 16 + g;
        float sc0 = ss[co], sh0 = sb[co];
        float sc1 = ss[co + 8], sh1 = sb[co + 8];
#pragma unroll
        for (int nt = 0; nt < 8; nt++) {
            int n = n0w + nt * 8 + (lane & 3) * 2;
            int r = n >> 7, wx = n & 127;
            float* o0p = out + (((size_t)b * CS + co) * Hh + h0 + r) * Ww + wx;
            float* o1p = out + (((size_t)b * CS + co + 8) * Hh + h0 + r) * Ww + wx;
            float2 o0 = make_float2(fmaxf(fmaf(acc[mt][nt][0], sc0, sh0), 0.f),
                                    fmaxf(fmaf(acc[mt][nt][1], sc0, sh0), 0.f));
            float2 o1 = make_float2(fmaxf(fmaf(acc[mt][nt][2], sc1, sh1), 0.f),
                                    fmaxf(fmaf(acc[mt][nt][3], sc1, sh1), 0.f));
            *(float2*)o0p = o0;
            *(float2*)o1p = o1;
        }
    }
}

// ============================================================
extern "C" void kernel_launch(void* const* d_in, const int* in_sizes, int n_in,
                              void* d_out, int out_size)
{
    (void)in_sizes; (void)n_in; (void)out_size;
    const float* x        = (const float*)d_in[0];
    const float* up       = (const float*)d_in[1];
    const float* qW       = (const float*)d_in[2];
    const float* q_scale  = (const float*)d_in[3];
    const float* q_shift  = (const float*)d_in[4];
    const float* kW       = (const float*)d_in[5];
    const float* k_scale  = (const float*)d_in[6];
    const float* k_shift  = (const float*)d_in[7];
    const float* vW       = (const float*)d_in[8];
    const float* v_scale  = (const float*)d_in[9];
    const float* v_shift  = (const float*)d_in[10];
    const float* oW       = (const float*)d_in[11];
    const float* o_scale  = (const float*)d_in[12];
    const float* o_shift  = (const float*)d_in[13];
    const float* sW       = (const float*)d_in[14];
    const float* s_scale  = (const float*)d_in[15];
    const float* s_shift  = (const float*)d_in[16];
    float* out = (float*)d_out;

    cudaFuncSetAttribute(k_qk_mma, cudaFuncAttributeMaxDynamicSharedMemorySize, 69632);
    cudaFuncSetAttribute(k_v_mma, cudaFuncAttributeMaxDynamicSharedMemorySize, 66560);
    cudaFuncSetAttribute(k_conv_mma, cudaFuncAttributeMaxDynamicSharedMemorySize, 70656);

    k_pack_qk<<<64, 256>>>(qW, kW);
    k_pack_v<<<128, 256>>>(vW);
    k_pack_conv<<<576, 256>>>(sW);
    k_packx<<<32768, 256>>>(x);
    k_qk_mma<<<dim3(HW / 128, Bn), 256, 69632>>>(q_scale, q_shift, k_scale, k_shift);
    k_v_mma<<<dim3(HW / 128, 2, Bn), 256, 66560>>>(v_scale, v_shift);
    k_sim_mma<<<dim3(NCH, Bn), 256>>>();
    k_simreduce<<<256, 256>>>();
    k_m2<<<Bn * CQK, 256>>>(oW);
    k_ctx<<<dim3(Hh, 2, Bn), 256>>>(x, up, o_scale, o_shift);
    k_conv_mma<<<dim3(Hh / 2, 2, Bn), 256, 70656>>>(s_scale, s_shift, out);
}

// round 5
// speedup vs baseline: 3.5996x; 1.1279x over previous
#include <cuda_runtime.h>
#include <math.h>
#include <stdint.h>

#define Bn   4
#define CIN  256
#define CQK  64
#define CS   128
#define Hh   128
#define Ww   128
#define HW   (Hh*Ww)
#define NCH  64
#define PIX_PER_CHUNK (HW/NCH)     // 256

// ---- scratch ----
__device__ float g_simp[Bn*NCH*CQK*CIN];   // 16MB
__device__ float g_sim [Bn*CQK*CIN];

// packed tf32 pair buffers (zero-initialized .bss; borders of g_ft stay zero)
__device__ __align__(16) uint2 g_Aqk[16384];            // qk weights
__device__ __align__(16) uint2 g_Av [32768];            // v weights
__device__ __align__(16) uint2 g_wp2[147456];           // conv weights
__device__ __align__(16) uint2 g_AM2[Bn*8192];          // M2 packed: [b][krow8][co256][kk4]
__device__ __align__(16) uint2 g_xt [Bn*8*16*HW];       // x packed: [(b*8+it)*16+kkb][n]
__device__ __align__(16) uint2 g_qnt[Bn*32*HW];         // qn packed, channel pairs: [b][row32][n]
__device__ __align__(16) uint2 g_knt[Bn*64*(HW/2)];     // kn packed, pixel pairs: [b][m64][pair]
__device__ __align__(16) uint2 g_vt [Bn*256*(HW/2)];    // v packed, pixel pairs: [b][co256][pair]
__device__ __align__(16) uint2 g_ft [Bn*128*130*132];   // fuse packed+padded: [b*128+ch*8+kkb][h+1][w+1]

__device__ __forceinline__ uint32_t f2tf(float f) {
    uint32_t u; asm("cvt.rna.tf32.f32 %0, %1;" : "=r"(u) : "f"(f)); return u;
}

__device__ __forceinline__ void mma8(float* c, uint2 a01, uint2 a13, uint2 b) {
    asm volatile(
        "mma.sync.aligned.m16n8k8.row.col.f32.tf32.tf32.f32 "
        "{%0,%1,%2,%3}, {%4,%5,%6,%7}, {%8,%9}, {%0,%1,%2,%3};"
        : "+f"(c[0]), "+f"(c[1]), "+f"(c[2]), "+f"(c[3])
        : "r"(a01.x), "r"(a13.x), "r"(a01.y), "r"(a13.y), "r"(b.x), "r"(b.y));
}

__device__ __forceinline__ void cpa16(uint32_t saddr, const void* g) {
    asm volatile("cp.async.cg.shared.global [%0], [%1], 16;" :: "r"(saddr), "l"(g));
}
__device__ __forceinline__ void cpa_commit() { asm volatile("cp.async.commit_group;"); }
__device__ __forceinline__ void cpa_wait0()  { asm volatile("cp.async.wait_group 0;" ::: "memory"); }

// ============ pack kernels ============
__global__ void k_pack_qk(const float* __restrict__ qW, const float* __restrict__ kW)
{
    int idx = blockIdx.x * 256 + threadIdx.x;
    int kk = idx & 3, m = (idx >> 2) & 127, kb = idx >> 9;
    int k0 = kb * 8 + kk;
    const float* wr = (m < 64) ? (qW + (size_t)m * CIN) : (kW + (size_t)(m - 64) * CIN);
    g_Aqk[idx] = make_uint2(f2tf(wr[k0]), f2tf(wr[k0 + 4]));
}

__global__ void k_pack_v(const float* __restrict__ vW)
{
    int idx = blockIdx.x * 256 + threadIdx.x;
    int kk = idx & 3, m = (idx >> 2) & 255, kb = idx >> 10;
    int k0 = kb * 8 + kk;
    const float* wr = vW + (size_t)m * CIN;
    g_Av[idx] = make_uint2(f2tf(wr[k0]), f2tf(wr[k0 + 4]));
}

__global__ void k_pack_conv(const float* __restrict__ sW)
{
    int idx = blockIdx.x * 256 + threadIdx.x;
    int r = idx & 1023, s = idx >> 10;
    int kk = r & 3, co = (r >> 2) & 127, kb = r >> 9;
    int tap = s % 3, t2 = s / 3, ch = t2 & 15, dh = t2 >> 4;
    int ci = ch * 16 + kb * 8 + kk;
    float w0 = sW[((size_t)co * CIN + ci) * 9 + dh * 3 + tap];
    float w1 = sW[((size_t)co * CIN + ci + 4) * 9 + dh * 3 + tap];
    g_wp2[idx] = make_uint2(f2tf(w0), f2tf(w1));
}

// x -> tf32 pair layout, 4 pixels per thread
__global__ void k_packx(const float* __restrict__ x)
{
    int idx = blockIdx.x * 256 + threadIdx.x;   // < 2097152
    int n4 = (idx & 4095) * 4;
    int kkb = (idx >> 12) & 15;
    int it = (idx >> 16) & 7;
    int b = idx >> 19;
    int k0 = it * 32 + ((kkb >> 2) << 3) + (kkb & 3);
    const float* xb = x + ((size_t)b * CIN + k0) * HW + n4;
    float4 lo = *(const float4*)xb;
    float4 hi = *(const float4*)(xb + 4 * HW);
    uint2* dst = g_xt + ((size_t)((b * 8 + it) * 16 + kkb)) * HW + n4;
    *(uint4*)dst = make_uint4(f2tf(lo.x), f2tf(hi.x), f2tf(lo.y), f2tf(hi.y));
    *(uint4*)(dst + 2) = make_uint4(f2tf(lo.z), f2tf(hi.z), f2tf(lo.w), f2tf(hi.w));
}

// ============ K1: q,k projections + BN + L2 norm -> packed g_qnt / g_knt ============
// dyn smem: Asm 2x2048 uint2, Bsm 2x2112 uint2, Sq 4x128 f32, Nn 2x128 f32 = 69632 B
__global__ void __launch_bounds__(256, 2)
k_qk_mma(const float* __restrict__ qs, const float* __restrict__ qb,
         const float* __restrict__ kscale, const float* __restrict__ kshift)
{
    extern __shared__ uint2 dynsm[];
    uint2* Asm = dynsm;              // 2 x 2048
    uint2* Bsm = dynsm + 4096;       // 2 x 2112
    float* Sq  = (float*)(dynsm + 8320);
    float* Nn  = Sq + 512;

    const int b = blockIdx.y, n0 = blockIdx.x * 128;
    const int tid = threadIdx.x, lane = tid & 31, w = tid >> 5;
    const int g = lane >> 2, kk = lane & 3;
    const int mg = w >> 1, ng = w & 1;
    const int m0w = mg * 32, n0w = ng * 64;

    const uint32_t aBase = (uint32_t)__cvta_generic_to_shared(dynsm);
    const uint2* xtb = g_xt + (size_t)b * 8 * 16 * HW + n0;

    float acc[2][8][4];
#pragma unroll
    for (int mt = 0; mt < 2; mt++)
#pragma unroll
        for (int nt = 0; nt < 8; nt++)
#pragma unroll
            for (int i = 0; i < 4; i++) acc[mt][nt][i] = 0.f;

#pragma unroll
    for (int i = 0; i < 4; i++) {
        int j = i * 256 + tid;
        cpa16(aBase + j * 16, g_Aqk + j * 2);
    }
#pragma unroll
    for (int i = 0; i < 4; i++) {
        int j = i * 256 + tid;
        int kkb = j >> 6, npair = (j & 63) * 2;
        cpa16(aBase + 4096 * 8 + (kkb * 132 + npair) * 8,
              xtb + (size_t)kkb * HW + npair);
    }
    cpa_commit();
    cpa_wait0();
    __syncthreads();

    for (int it = 0; it < 8; it++) {
        int cur = it & 1, nxt = cur ^ 1;
        if (it < 7) {
#pragma unroll
            for (int i = 0; i < 4; i++) {
                int j = i * 256 + tid;
                cpa16(aBase + nxt * 16384 + j * 16, g_Aqk + (it + 1) * 2048 + j * 2);
            }
#pragma unroll
            for (int i = 0; i < 4; i++) {
                int j = i * 256 + tid;
                int kkb = j >> 6, npair = (j & 63) * 2;
                cpa16(aBase + 4096 * 8 + nxt * 16896 + (kkb * 132 + npair) * 8,
                      xtb + (size_t)((it + 1) * 16 + kkb) * HW + npair);
            }
            cpa_commit();
        }
        const uint2* Ac = Asm + cur * 2048;
        const uint2* Bc = Bsm + cur * 2112;
#pragma unroll
        for (int kb = 0; kb < 4; kb++) {
            uint2 a01[2], a13[2];
#pragma unroll
            for (int mt = 0; mt < 2; mt++) {
                a01[mt] = Ac[(kb * 128 + m0w + mt * 16 + g) * 4 + kk];
                a13[mt] = Ac[(kb * 128 + m0w + mt * 16 + 8 + g) * 4 + kk];
            }
#pragma unroll
            for (int nt = 0; nt < 8; nt++) {
                uint2 bb = Bc[(kb * 4 + kk) * 132 + n0w + nt * 8 + g];
                mma8(acc[0][nt], a01[0], a13[0], bb);
                mma8(acc[1][nt], a01[1], a13[1], bb);
            }
        }
        cpa_wait0();
        __syncthreads();
    }

    // BN + column sums of squares
    float sq[8][2];
#pragma unroll
    for (int nt = 0; nt < 8; nt++) { sq[nt][0] = 0.f; sq[nt][1] = 0.f; }
#pragma unroll
    for (int mt = 0; mt < 2; mt++) {
        int r0 = m0w + mt * 16 + g, r1 = r0 + 8;
        bool isq = (r0 < 64);
        float sc0 = isq ? qs[r0] : kscale[r0 - 64];
        float sh0 = isq ? qb[r0] : kshift[r0 - 64];
        float sc1 = isq ? qs[r1] : kscale[r1 - 64];
        float sh1 = isq ? qb[r1] : kshift[r1 - 64];
#pragma unroll
        for (int nt = 0; nt < 8; nt++) {
            float v0 = fmaf(acc[mt][nt][0], sc0, sh0);
            float v1 = fmaf(acc[mt][nt][1], sc0, sh0);
            float v2 = fmaf(acc[mt][nt][2], sc1, sh1);
            float v3 = fmaf(acc[mt][nt][3], sc1, sh1);
            acc[mt][nt][0] = v0; acc[mt][nt][1] = v1;
            acc[mt][nt][2] = v2; acc[mt][nt][3] = v3;
            sq[nt][0] += v0 * v0 + v2 * v2;
            sq[nt][1] += v1 * v1 + v3 * v3;
        }
    }
#pragma unroll
    for (int nt = 0; nt < 8; nt++) {
#pragma unroll
        for (int o = 4; o < 32; o <<= 1) {
            sq[nt][0] += __shfl_xor_sync(0xffffffffu, sq[nt][0], o);
            sq[nt][1] += __shfl_xor_sync(0xffffffffu, sq[nt][1], o);
        }
    }
    if (lane < 4) {
#pragma unroll
        for (int nt = 0; nt < 8; nt++) {
            int c = n0w + nt * 8 + lane * 2;
            Sq[mg * 128 + c] = sq[nt][0];
            Sq[mg * 128 + c + 1] = sq[nt][1];
        }
    }
    __syncthreads();
    {
        int col = tid & 127, half = tid >> 7;
        float s = Sq[half * 256 + col] + Sq[half * 256 + 128 + col];
        Nn[half * 128 + col] = 1.f / fmaxf(sqrtf(s), 1e-12f);
    }
    __syncthreads();

    if (mg < 2) {
        // q half -> g_qnt: channel pairs (ch, ch+4) via shfl_xor 16
#pragma unroll
        for (int mt = 0; mt < 2; mt++) {
            int r0 = m0w + mt * 16 + g;
#pragma unroll
            for (int nt = 0; nt < 8; nt++) {
                int c = n0w + nt * 8 + (lane & 3) * 2;
                float i0 = Nn[c], i1 = Nn[c + 1];
                float v0 = acc[mt][nt][0] * i0, v1 = acc[mt][nt][1] * i1;
                float v2 = acc[mt][nt][2] * i0, v3 = acc[mt][nt][3] * i1;
                float p0 = __shfl_xor_sync(0xffffffffu, v0, 16);
                float p1 = __shfl_xor_sync(0xffffffffu, v1, 16);
                float p2 = __shfl_xor_sync(0xffffffffu, v2, 16);
                float p3 = __shfl_xor_sync(0xffffffffu, v3, 16);
                if (g < 4) {
                    int row0 = (r0 >> 3) * 4 + g;
                    int row1 = ((r0 + 8) >> 3) * 4 + g;
                    *(uint4*)(g_qnt + (size_t)(b * 32 + row0) * HW + n0 + c) =
                        make_uint4(f2tf(v0), f2tf(p0), f2tf(v1), f2tf(p1));
                    *(uint4*)(g_qnt + (size_t)(b * 32 + row1) * HW + n0 + c) =
                        make_uint4(f2tf(v2), f2tf(p2), f2tf(v3), f2tf(p3));
                }
            }
        }
    } else {
        // k half -> g_knt: pixel pairs (p, p+4) via shfl_xor 2
#pragma unroll
        for (int mt = 0; mt < 2; mt++) {
            int r0 = m0w + mt * 16 + g - 64;
#pragma unroll
            for (int nt = 0; nt < 8; nt++) {
                int c = n0w + nt * 8 + (lane & 3) * 2;
                float i0 = Nn[128 + c], i1 = Nn[128 + c + 1];
                float v0 = acc[mt][nt][0] * i0, v1 = acc[mt][nt][1] * i1;
                float v2 = acc[mt][nt][2] * i0, v3 = acc[mt][nt][3] * i1;
                float p0 = __shfl_xor_sync(0xffffffffu, v0, 2);
                float p1 = __shfl_xor_sync(0xffffffffu, v1, 2);
                float p2 = __shfl_xor_sync(0xffffffffu, v2, 2);
                float p3 = __shfl_xor_sync(0xffffffffu, v3, 2);
                if ((lane & 2) == 0) {
                    size_t pb = (size_t)((n0 + c) >> 3) * 4 + (c & 3);
                    *(uint4*)(g_knt + (size_t)(b * 64 + r0) * 8192 + pb) =
                        make_uint4(f2tf(v0), f2tf(p0), f2tf(v1), f2tf(p1));
                    *(uint4*)(g_knt + (size_t)(b * 64 + r0 + 8) * 8192 + pb) =
                        make_uint4(f2tf(v2), f2tf(p2), f2tf(v3), f2tf(p3));
                }
            }
        }
    }
}

// ============ K2: v projection + BN + ReLU -> packed g_vt ============
// dyn smem: Asm 2x2048 + Bsm 2x2112 uint2 = 66560 B
__global__ void __launch_bounds__(256, 2)
k_v_mma(const float* __restrict__ vs, const float* __restrict__ vb)
{
    extern __shared__ uint2 dynsm[];
    uint2* Asm = dynsm;
    uint2* Bsm = dynsm + 4096;

    const int b = blockIdx.z, co0 = blockIdx.y * 128, n0 = blockIdx.x * 128;
    const int tid = threadIdx.x, lane = tid & 31, w = tid >> 5;
    const int g = lane >> 2, kk = lane & 3;
    const int mg = w >> 1, ng = w & 1;
    const int m0w = mg * 32, n0w = ng * 64;

    const uint32_t aBase = (uint32_t)__cvta_generic_to_shared(dynsm);
    const uint2* xtb = g_xt + (size_t)b * 8 * 16 * HW + n0;

    float acc[2][8][4];
#pragma unroll
    for (int mt = 0; mt < 2; mt++)
#pragma unroll
        for (int nt = 0; nt < 8; nt++)
#pragma unroll
            for (int i = 0; i < 4; i++) acc[mt][nt][i] = 0.f;

#pragma unroll
    for (int i = 0; i < 4; i++) {
        int j = i * 256 + tid;
        int u = j * 2, kbl = u >> 9, r = u & 511;
        cpa16(aBase + u * 8, g_Av + (size_t)kbl * 1024 + co0 * 4 + r);
    }
#pragma unroll
    for (int i = 0; i < 4; i++) {
        int j = i * 256 + tid;
        int kkb = j >> 6, npair = (j & 63) * 2;
        cpa16(aBase + 4096 * 8 + (kkb * 132 + npair) * 8,
              xtb + (size_t)kkb * HW + npair);
    }
    cpa_commit();
    cpa_wait0();
    __syncthreads();

    for (int it = 0; it < 8; it++) {
        int cur = it & 1, nxt = cur ^ 1;
        if (it < 7) {
#pragma unroll
            for (int i = 0; i < 4; i++) {
                int j = i * 256 + tid;
                int u = j * 2, kbl = u >> 9, r = u & 511;
                cpa16(aBase + nxt * 16384 + u * 8,
                      g_Av + (size_t)((it + 1) * 4 + kbl) * 1024 + co0 * 4 + r);
            }
#pragma unroll
            for (int i = 0; i < 4; i++) {
                int j = i * 256 + tid;
                int kkb = j >> 6, npair = (j & 63) * 2;
                cpa16(aBase + 4096 * 8 + nxt * 16896 + (kkb * 132 + npair) * 8,
                      xtb + (size_t)((it + 1) * 16 + kkb) * HW + npair);
            }
            cpa_commit();
        }
        const uint2* Ac = Asm + cur * 2048;
        const uint2* Bc = Bsm + cur * 2112;
#pragma unroll
        for (int kb = 0; kb < 4; kb++) {
            uint2 a01[2], a13[2];
#pragma unroll
            for (int mt = 0; mt < 2; mt++) {
                a01[mt] = Ac[(kb * 128 + m0w + mt * 16 + g) * 4 + kk];
                a13[mt] = Ac[(kb * 128 + m0w + mt * 16 + 8 + g) * 4 + kk];
            }
#pragma unroll
            for (int nt = 0; nt < 8; nt++) {
                uint2 bb = Bc[(kb * 4 + kk) * 132 + n0w + nt * 8 + g];
                mma8(acc[0][nt], a01[0], a13[0], bb);
                mma8(acc[1][nt], a01[1], a13[1], bb);
            }
        }
        cpa_wait0();
        __syncthreads();
    }

    // epilogue: BN + ReLU, pack pixel pairs via shfl_xor 2 -> g_vt
#pragma unroll
    for (int mt = 0; mt < 2; mt++) {
        int co = co0 + m0w + mt * 16 + g;
        float sc0 = vs[co], sh0 = vb[co];
        float sc1 = vs[co + 8], sh1 = vb[co + 8];
#pragma unroll
        for (int nt = 0; nt < 8; nt++) {
            int c = n0w + nt * 8 + (lane & 3) * 2;
            float f0 = fmaxf(fmaf(acc[mt][nt][0], sc0, sh0), 0.f);
            float f1 = fmaxf(fmaf(acc[mt][nt][1], sc0, sh0), 0.f);
            float f2 = fmaxf(fmaf(acc[mt][nt][2], sc1, sh1), 0.f);
            float f3 = fmaxf(fmaf(acc[mt][nt][3], sc1, sh1), 0.f);
            float p0 = __shfl_xor_sync(0xffffffffu, f0, 2);
            float p1 = __shfl_xor_sync(0xffffffffu, f1, 2);
            float p2 = __shfl_xor_sync(0xffffffffu, f2, 2);
            float p3 = __shfl_xor_sync(0xffffffffu, f3, 2);
            if ((lane & 2) == 0) {
                size_t pb = (size_t)((n0 + c) >> 3) * 4 + (c & 3);
                *(uint4*)(g_vt + (size_t)(b * 256 + co) * 8192 + pb) =
                    make_uint4(f2tf(f0), f2tf(p0), f2tf(f1), f2tf(p1));
                *(uint4*)(g_vt + (size_t)(b * 256 + co + 8) * 8192 + pb) =
                    make_uint4(f2tf(f2), f2tf(p2), f2tf(f3), f2tf(p3));
            }
        }
    }
}

// ============ K3: partial sim = kn @ v^T (pre-packed, cp.async double-buffered) ============
// dyn smem: A 2x1152 + B 2x4608 uint2 = 92160 B
__global__ void __launch_bounds__(256, 2) k_sim_mma()
{
    extern __shared__ uint2 dynsm[];

    const int b = blockIdx.y, ch = blockIdx.x;
    const int p0 = ch * PIX_PER_CHUNK;
    const int tid = threadIdx.x, lane = tid & 31, w = tid >> 5;
    const int g = lane >> 2, kk = lane & 3;
    const int mg = w >> 2, ng = w & 3;
    const int m0w = mg * 32, n0w = ng * 64;
    const uint32_t smBase = (uint32_t)__cvta_generic_to_shared(dynsm);

    float acc[2][8][4];
#pragma unroll
    for (int mt = 0; mt < 2; mt++)
#pragma unroll
        for (int nt = 0; nt < 8; nt++)
#pragma unroll
            for (int i = 0; i < 4; i++) acc[mt][nt][i] = 0.f;

    auto fill = [&](int it, int stage) {
        int base = (p0 + it * 32) >> 1;        // pair idx base
#pragma unroll
        for (int i = 0; i < 2; i++) {
            int j = i * 256 + tid;
            int m = j >> 3, seg = j & 7;
            cpa16(smBase + (stage * 1152 + m * 18 + seg * 2) * 8,
                  g_knt + (size_t)(b * 64 + m) * 8192 + base + seg * 2);
        }
#pragma unroll
        for (int i = 0; i < 8; i++) {
            int j = i * 256 + tid;
            int n = j >> 3, seg = j & 7;
            cpa16(smBase + (2304 + stage * 4608 + n * 18 + seg * 2) * 8,
                  g_vt + (size_t)(b * 256 + n) * 8192 + base + seg * 2);
        }
    };

    fill(0, 0);
    cpa_commit();
    cpa_wait0();
    __syncthreads();

    for (int it = 0; it < 8; it++) {
        int cur = it & 1, nxt = cur ^ 1;
        if (it < 7) { fill(it + 1, nxt); cpa_commit(); }
        const uint2* Ac = dynsm + cur * 1152;
        const uint2* Bc = dynsm + 2304 + cur * 4608;
#pragma unroll
        for (int kb = 0; kb < 4; kb++) {
            uint2 a01[2], a13[2];
#pragma unroll
            for (int mt = 0; mt < 2; mt++) {
                a01[mt] = Ac[(m0w + mt * 16 + g) * 18 + kb * 4 + kk];
                a13[mt] = Ac[(m0w + mt * 16 + 8 + g) * 18 + kb * 4 + kk];
            }
#pragma unroll
            for (int nt = 0; nt < 8; nt++) {
                uint2 bb = Bc[(n0w + nt * 8 + g) * 18 + kb * 4 + kk];
                mma8(acc[0][nt], a01[0], a13[0], bb);
                mma8(acc[1][nt], a01[1], a13[1], bb);
            }
        }
        cpa_wait0();
        __syncthreads();
    }

    float* outp = g_simp + (size_t)(b * NCH + ch) * CQK * CIN;
#pragma unroll
    for (int mt = 0; mt < 2; mt++) {
        int r = m0w + mt * 16 + g;
#pragma unroll
        for (int nt = 0; nt < 8; nt++) {
            int c = n0w + nt * 8 + (lane & 3) * 2;
            *(float2*)&outp[(size_t)r * CIN + c] = make_float2(acc[mt][nt][0], acc[mt][nt][1]);
            *(float2*)&outp[(size_t)(r + 8) * CIN + c] = make_float2(acc[mt][nt][2], acc[mt][nt][3]);
        }
    }
}

// K3b: reduce partials
__global__ void k_simreduce()
{
    int o = blockIdx.x * 256 + threadIdx.x;
    int b = o / (CQK * CIN);
    int cv = o - b * (CQK * CIN);
    float s = 0.f;
#pragma unroll 8
    for (int ch = 0; ch < NCH; ch++)
        s += g_simp[((size_t)(b * NCH + ch)) * CQK * CIN + cv];
    g_sim[o] = s;
}

// K4a: M2 = oW @ sim^T, written directly as packed tf32 pairs g_AM2
__global__ void k_m2(const float* __restrict__ oW)
{
    __shared__ float ssm[CIN];
    const int b = blockIdx.x >> 6;
    const int c = blockIdx.x & 63;
    const int o = threadIdx.x;
    ssm[o] = g_sim[((size_t)b * CQK + c) * CIN + o];
    __syncthreads();
    float s = 0.f;
#pragma unroll 8
    for (int v = 0; v < CIN; v++) s = fmaf(oW[(size_t)o * CIN + v], ssm[v], s);
    int krow = c >> 3, rem = c & 7;
    int kkv = rem & 3;
    ((uint32_t*)g_AM2)[(size_t)b * 16384 + (krow * 256 + o) * 8 + kkv * 2 + (rem >> 2)] = f2tf(s);
}

// ============ K4: ctx mma: fuse = relu(BN(M2 @ qn)) + x + up -> packed g_ft ============
// dyn smem: Asm 4096 + Bsm 4224 uint2 + upH 8192 f32 = 99328 B
__global__ void __launch_bounds__(256, 2)
k_ctx_mma(const float* __restrict__ x, const float* __restrict__ up,
          const float* __restrict__ os, const float* __restrict__ ob)
{
    extern __shared__ uint2 dynsm[];
    uint2* Asm = dynsm;              // 4096
    uint2* Bsm = dynsm + 4096;       // 32 x 132
    float* upH = (float*)(dynsm + 8320);  // [128][64]

    const int b = blockIdx.z;
    const int co0 = blockIdx.y * 128;
    const int h = blockIdx.x;
    const int n0 = h * Ww;
    const int tid = threadIdx.x, lane = tid & 31, w = tid >> 5;
    const int g = lane >> 2, kk = lane & 3;
    const int mg = w >> 1, ng = w & 1;
    const int m0w = mg * 32, n0w = ng * 64;
    const uint32_t aBase = (uint32_t)__cvta_generic_to_shared(dynsm);

    // A: M2 co-half, B: qnt row tile
#pragma unroll
    for (int i = 0; i < 8; i++) {
        int jj = i * 256 + tid;           // < 2048
        int u = jj * 2;
        int kk2 = u & 3, m = (u >> 2) & 127, krow = u >> 9;
        cpa16(aBase + u * 8, g_AM2 + (size_t)b * 8192 + krow * 1024 + (co0 + m) * 4 + kk2);
    }
#pragma unroll
    for (int i = 0; i < 8; i++) {
        int jj = i * 256 + tid;           // < 2048
        int row = jj >> 6, colpair = (jj & 63) * 2;
        cpa16(aBase + 4096 * 8 + (row * 132 + colpair) * 8,
              g_qnt + (size_t)(b * 32 + row) * HW + n0 + colpair);
    }
    cpa_commit();

    // upsample row interp
    {
        float shf = 0.5f * h - 0.25f;
        int h0 = (int)floorf(shf);
        float wh1 = shf - (float)h0;
        int h0c = h0 < 0 ? 0 : h0;
        int h1c = (h0 + 1) > 63 ? 63 : (h0 + 1);
        const float* ub = up + ((size_t)(b * CIN + co0)) * 64 * 64;
#pragma unroll
        for (int i = 0; i < 32; i++) {
            int idx = i * 256 + tid;
            int r = idx >> 6, sw = idx & 63;
            upH[r * 64 + sw] = (1.f - wh1) * ub[(r * 64 + h0c) * 64 + sw]
                             + wh1 * ub[(r * 64 + h1c) * 64 + sw];
        }
    }
    cpa_wait0();
    __syncthreads();

    float acc[2][8][4];
#pragma unroll
    for (int mt = 0; mt < 2; mt++)
#pragma unroll
        for (int nt = 0; nt < 8; nt++)
#pragma unroll
            for (int i = 0; i < 4; i++) acc[mt][nt][i] = 0.f;

#pragma unroll
    for (int s = 0; s < 8; s++) {
        uint2 a01[2], a13[2];
#pragma unroll
        for (int mt = 0; mt < 2; mt++) {
            a01[mt] = Asm[(s * 128 + m0w + mt * 16 + g) * 4 + kk];
            a13[mt] = Asm[(s * 128 + m0w + mt * 16 + 8 + g) * 4 + kk];
        }
#pragma unroll
        for (int nt = 0; nt < 8; nt++) {
            uint2 bb = Bsm[(s * 4 + kk) * 132 + n0w + nt * 8 + g];
            mma8(acc[0][nt], a01[0], a13[0], bb);
            mma8(acc[1][nt], a01[1], a13[1], bb);
        }
    }

    // epilogue: BN+ReLU + residual + upsample, pack channel pairs -> g_ft
    const float* xb = x + ((size_t)b * CIN + co0) * HW + n0;
#pragma unroll
    for (int mt = 0; mt < 2; mt++) {
        int m = m0w + mt * 16 + g;
        int co = co0 + m;
        float sc0 = os[co], sh0 = ob[co];
        float sc1 = os[co + 8], sh1 = ob[co + 8];
#pragma unroll
        for (int nt = 0; nt < 8; nt++) {
            int c0 = n0w + nt * 8 + (lane & 3) * 2;
            int c1 = c0 + 1;
            float sw0 = 0.5f * c0 - 0.25f, sw1 = 0.5f * c1 - 0.25f;
            int wa0 = (int)floorf(sw0), wa1 = (int)floorf(sw1);
            float t0 = sw0 - (float)wa0, t1 = sw1 - (float)wa1;
            int w00 = wa0 < 0 ? 0 : wa0, w01 = (wa0 + 1) > 63 ? 63 : (wa0 + 1);
            int w10 = wa1 < 0 ? 0 : wa1, w11 = (wa1 + 1) > 63 ? 63 : (wa1 + 1);

            float u0a = (1.f - t0) * upH[m * 64 + w00] + t0 * upH[m * 64 + w01];
            float u1a = (1.f - t1) * upH[m * 64 + w10] + t1 * upH[m * 64 + w11];
            float u0b = (1.f - t0) * upH[(m + 8) * 64 + w00] + t0 * upH[(m + 8) * 64 + w01];
            float u1b = (1.f - t1) * upH[(m + 8) * 64 + w10] + t1 * upH[(m + 8) * 64 + w11];

            float f0 = fmaxf(fmaf(acc[mt][nt][0], sc0, sh0), 0.f) + xb[(size_t)m * HW + c0] + u0a;
            float f1 = fmaxf(fmaf(acc[mt][nt][1], sc0, sh0), 0.f) + xb[(size_t)m * HW + c1] + u1a;
            float f2 = fmaxf(fmaf(acc[mt][nt][2], sc1, sh1), 0.f) + xb[(size_t)(m + 8) * HW + c0] + u0b;
            float f3 = fmaxf(fmaf(acc[mt][nt][3], sc1, sh1), 0.f) + xb[(size_t)(m + 8) * HW + c1] + u1b;

            float p0 = __shfl_xor_sync(0xffffffffu, f0, 16);
            float p1 = __shfl_xor_sync(0xffffffffu, f1, 16);
            float p2 = __shfl_xor_sync(0xffffffffu, f2, 16);
            float p3 = __shfl_xor_sync(0xffffffffu, f3, 16);
            if (g < 4) {
                int ch16 = co >> 4;
                size_t rowA = (size_t)(b * 128 + ch16 * 8 + g);
                size_t rowB = rowA + 4;
                uint2* dA = g_ft + (rowA * 130 + h + 1) * 132 + 1 + c0;
                uint2* dB = g_ft + (rowB * 130 + h + 1) * 132 + 1 + c0;
                dA[0] = make_uint2(f2tf(f0), f2tf(p0));
                dA[1] = make_uint2(f2tf(f1), f2tf(p1));
                dB[0] = make_uint2(f2tf(f2), f2tf(p2));
                dB[1] = make_uint2(f2tf(f3), f2tf(p3));
            }
        }
    }
}

// ============ K5: 3x3 conv, 2 rows x 64 co x 128 w, 32-stage pipeline ============
// dyn smem: Ism 2x2112 + Wsm 2x2304 uint2 = 70656 B
__global__ void __launch_bounds__(256, 2)
k_conv_mma(const float* __restrict__ ss, const float* __restrict__ sb,
           float* __restrict__ out)
{
    extern __shared__ uint2 csm[];
    uint2* Ism = csm;            // 2 x 2112: [row4][kkbl4][132]
    uint2* Wsm = csm + 4224;     // 2 x 2304: [dh*3+tap][256]

    const int h0 = blockIdx.x * 2;
    const int co0 = blockIdx.y * 64;
    const int b = blockIdx.z;
    const int tid = threadIdx.x, lane = tid & 31, w = tid >> 5;
    const int g = lane >> 2, kk = lane & 3;
    const int mg = w >> 2, ng = w & 3;
    const int m0w = mg * 32, n0w = ng * 64;
    const uint32_t smBase = (uint32_t)__cvta_generic_to_shared(csm);

    float acc[2][8][4];
#pragma unroll
    for (int mt = 0; mt < 2; mt++)
#pragma unroll
        for (int nt = 0; nt < 8; nt++)
#pragma unroll
            for (int i = 0; i < 4; i++) acc[mt][nt][i] = 0.f;

    const uint2* ftb = g_ft + (size_t)b * 128 * 130 * 132;

    auto fill = [&](int it, int stage) {
        int ch = it >> 1, kbh = it & 1;
        for (int j = tid; j < 1056; j += 256) {
            int rowplane = j / 66;
            int colpair = (j - rowplane * 66) * 2;
            int row = rowplane >> 2, kkbl = rowplane & 3;
            cpa16(smBase + (stage * 2112 + (row * 4 + kkbl) * 132 + colpair) * 8,
                  ftb + ((size_t)(ch * 8 + kbh * 4 + kkbl) * 130 + h0 + row) * 132 + colpair);
        }
        for (int j = tid; j < 1152; j += 256) {
            int u = j * 2;
            int grp = u >> 8, off = u & 255;
            int dh = grp / 3, tap = grp - dh * 3;
            cpa16(smBase + (4224 + stage * 2304 + grp * 256 + off) * 8,
                  g_wp2 + (size_t)(dh * 48 + ch * 3 + tap) * 1024 + kbh * 512 + co0 * 4 + off);
        }
    };

    fill(0, 0);
    cpa_commit();
    cpa_wait0();
    __syncthreads();

    for (int it = 0; it < 32; it++) {
        int cur = it & 1, nxt = cur ^ 1;
        if (it < 31) { fill(it + 1, nxt); cpa_commit(); }

        const uint2* Ic = Ism + cur * 2112;
        const uint2* Wc = Wsm + cur * 2304;
#pragma unroll
        for (int dh = 0; dh < 3; dh++) {
#pragma unroll
            for (int tap = 0; tap < 3; tap++) {
                const uint2* wb = Wc + (dh * 3 + tap) * 256;
                uint2 a01[2], a13[2];
#pragma unroll
                for (int mt = 0; mt < 2; mt++) {
                    a01[mt] = wb[(m0w + mt * 16 + g) * 4 + kk];
                    a13[mt] = wb[(m0w + mt * 16 + 8 + g) * 4 + kk];
                }
#pragma unroll
                for (int nt = 0; nt < 8; nt++) {
                    int n = n0w + nt * 8 + g;
                    int rrow = n >> 7, wx = n & 127;
                    uint2 bb = Ic[((rrow + dh) * 4 + kk) * 132 + wx + tap];
                    mma8(acc[0][nt], a01[0], a13[0], bb);
                    mma8(acc[1][nt], a01[1], a13[1], bb);
                }
            }
        }
        cpa_wait0();
        __syncthreads();
    }

#pragma unroll
    for (int mt = 0; mt < 2; mt++) {
        int co = co0 + m0w + mt * 16 + g;
        float sc0 = ss[co], sh0 = sb[co];
        float sc1 = ss[co + 8], sh1 = sb[co + 8];
#pragma unroll
        for (int nt = 0; nt < 8; nt++) {
            int n = n0w + nt * 8 + (lane & 3) * 2;
            int r = n >> 7, wx = n & 127;
            float* o0p = out + (((size_t)b * CS + co) * Hh + h0 + r) * Ww + wx;
            float* o1p = out + (((size_t)b * CS + co + 8) * Hh + h0 + r) * Ww + wx;
            float2 o0 = make_float2(fmaxf(fmaf(acc[mt][nt][0], sc0, sh0), 0.f),
                                    fmaxf(fmaf(acc[mt][nt][1], sc0, sh0), 0.f));
            float2 o1 = make_float2(fmaxf(fmaf(acc[mt][nt][2], sc1, sh1), 0.f),
                                    fmaxf(fmaf(acc[mt][nt][3], sc1, sh1), 0.f));
            *(float2*)o0p = o0;
            *(float2*)o1p = o1;
        }
    }
}

// ============================================================
extern "C" void kernel_launch(void* const* d_in, const int* in_sizes, int n_in,
                              void* d_out, int out_size)
{
    (void)in_sizes; (void)n_in; (void)out_size;
    const float* x        = (const float*)d_in[0];
    const float* up       = (const float*)d_in[1];
    const float* qW       = (const float*)d_in[2];
    const float* q_scale  = (const float*)d_in[3];
    const float* q_shift  = (const float*)d_in[4];
    const float* kW       = (const float*)d_in[5];
    const float* k_scale  = (const float*)d_in[6];
    const float* k_shift  = (const float*)d_in[7];
    const float* vW       = (const float*)d_in[8];
    const float* v_scale  = (const float*)d_in[9];
    const float* v_shift  = (const float*)d_in[10];
    const float* oW       = (const float*)d_in[11];
    const float* o_scale  = (const float*)d_in[12];
    const float* o_shift  = (const float*)d_in[13];
    const float* sW       = (const float*)d_in[14];
    const float* s_scale  = (const float*)d_in[15];
    const float* s_shift  = (const float*)d_in[16];
    float* out = (float*)d_out;

    cudaFuncSetAttribute(k_qk_mma, cudaFuncAttributeMaxDynamicSharedMemorySize, 69632);
    cudaFuncSetAttribute(k_v_mma, cudaFuncAttributeMaxDynamicSharedMemorySize, 66560);
    cudaFuncSetAttribute(k_sim_mma, cudaFuncAttributeMaxDynamicSharedMemorySize, 92160);
    cudaFuncSetAttribute(k_ctx_mma, cudaFuncAttributeMaxDynamicSharedMemorySize, 99328);
    cudaFuncSetAttribute(k_conv_mma, cudaFuncAttributeMaxDynamicSharedMemorySize, 70656);

    k_pack_qk<<<64, 256>>>(qW, kW);
    k_pack_v<<<128, 256>>>(vW);
    k_pack_conv<<<576, 256>>>(sW);
    k_packx<<<8192, 256>>>(x);
    k_qk_mma<<<dim3(HW / 128, Bn), 256, 69632>>>(q_scale, q_shift, k_scale, k_shift);
    k_v_mma<<<dim3(HW / 128, 2, Bn), 256, 66560>>>(v_scale, v_shift);
    k_sim_mma<<<dim3(NCH, Bn), 256, 92160>>>();
    k_simreduce<<<256, 256>>>();
    k_m2<<<Bn * CQK, 256>>>(oW);
    k_ctx_mma<<<dim3(Hh, 2, Bn), 256, 99328>>>(x, up, o_scale, o_shift);
    k_conv_mma<<<dim3(Hh / 2, 2, Bn), 256, 70656>>>(s_scale, s_shift, out);
}